// round 1
// baseline (speedup 1.0000x reference)
#include <cuda_runtime.h>
#include <cuda_bf16.h>
#include <math.h>
#include <float.h>

#define BATCH 2
#define SEQ   2048
#define DIM   1152
#define NHEAD 16
#define HDIM  72
#define O3    (3 * DIM)         // 3456
#define MROWS (BATCH * SEQ)     // 4096
#define BH    (BATCH * NHEAD)   // 32
#define SCALE 0.1178511301977579f   // 72^-0.5
#define LN_EPS 1e-5f

// ---------------- scratch (static device arrays; no allocations) ----------------
__device__ float g_qkv[(size_t)MROWS * O3];          // [B,N,3,H,D]  ~56.6 MB
__device__ float g_qt[(size_t)BH * SEQ * HDIM];      // [B,H,N,D]    ~18.9 MB  (pre-scaled by SCALE)
__device__ float g_kt[(size_t)BH * SEQ * HDIM];
__device__ float g_vt[(size_t)BH * SEQ * HDIM];
__device__ float g_S [(size_t)BH * SEQ * SEQ];       // [B,H,N,N]    ~536 MB
__device__ float g_ao[(size_t)MROWS * DIM];          // [B,N,C]      ~18.9 MB

// ---------------- classic 128x128x8 SGEMM, C[M,N] = A[M,K] @ B[N,K]^T (+bias) ---
__global__ __launch_bounds__(256)
void sgemm_nt(const float* __restrict__ A, const float* __restrict__ B,
              const float* __restrict__ bias, float* __restrict__ C,
              int M, int N, int K,
              long long sA, long long sB, long long sC)
{
    A += (long long)blockIdx.z * sA;
    B += (long long)blockIdx.z * sB;
    C += (long long)blockIdx.z * sC;

    __shared__ float As[8][128];
    __shared__ float Bs[8][128];

    const int tid = threadIdx.x;
    const int bm = blockIdx.y * 128;
    const int bn = blockIdx.x * 128;
    const int lr = tid >> 1;            // 0..127
    const int lc = (tid & 1) * 4;       // 0 or 4
    const float* Ap = A + (size_t)(bm + lr) * K + lc;
    const float* Bp = B + (size_t)(bn + lr) * K + lc;
    const int tx = tid & 15;
    const int ty = tid >> 4;

    float acc[8][8];
#pragma unroll
    for (int i = 0; i < 8; i++)
#pragma unroll
        for (int j = 0; j < 8; j++) acc[i][j] = 0.f;

    for (int k0 = 0; k0 < K; k0 += 8) {
        float4 a = *(const float4*)(Ap + k0);
        float4 b = *(const float4*)(Bp + k0);
        __syncthreads();
        As[lc + 0][lr] = a.x; As[lc + 1][lr] = a.y;
        As[lc + 2][lr] = a.z; As[lc + 3][lr] = a.w;
        Bs[lc + 0][lr] = b.x; Bs[lc + 1][lr] = b.y;
        Bs[lc + 2][lr] = b.z; Bs[lc + 3][lr] = b.w;
        __syncthreads();
#pragma unroll
        for (int kk = 0; kk < 8; kk++) {
            float ar[8], br[8];
#pragma unroll
            for (int i = 0; i < 8; i++) ar[i] = As[kk][ty * 8 + i];
#pragma unroll
            for (int j = 0; j < 8; j++) br[j] = Bs[kk][tx * 8 + j];
#pragma unroll
            for (int i = 0; i < 8; i++)
#pragma unroll
                for (int j = 0; j < 8; j++) acc[i][j] += ar[i] * br[j];
        }
    }

#pragma unroll
    for (int i = 0; i < 8; i++) {
        const size_t row = (size_t)(bm + ty * 8 + i);
#pragma unroll
        for (int j = 0; j < 8; j++) {
            const int col = bn + tx * 8 + j;
            float v = acc[i][j];
            if (bias) v += bias[col];
            C[row * N + col] = v;
        }
    }
}

// ------------- per-head LayerNorm(q,k) + SCALE on q + transpose, v copy --------
__global__ __launch_bounds__(256)
void ln_split(const float* __restrict__ qkv,
              const float* __restrict__ qg, const float* __restrict__ qb,
              const float* __restrict__ kg, const float* __restrict__ kb,
              float* __restrict__ qt, float* __restrict__ kt, float* __restrict__ vt)
{
    const int warps_per_block = 256 / 32;
    int task = blockIdx.x * warps_per_block + (threadIdx.x >> 5);
    if (task >= BATCH * SEQ * NHEAD) return;
    const int lane = threadIdx.x & 31;
    const int h = task % NHEAD;
    const int n = (task / NHEAD) % SEQ;
    const int b = task / (NHEAD * SEQ);

    const size_t ibase = ((size_t)(b * SEQ + n) * 3) * DIM + h * HDIM;
    const size_t obase = ((size_t)((b * NHEAD + h) * SEQ + n)) * HDIM;

    const float* q = qkv + ibase;
    const float* k = qkv + ibase + DIM;
    const float* v = qkv + ibase + 2 * DIM;

    // ---- q layernorm ----
    {
        float x0 = q[lane], x1 = q[lane + 32];
        float x2 = (lane < 8) ? q[lane + 64] : 0.f;
        float s = x0 + x1 + x2;
#pragma unroll
        for (int o = 16; o; o >>= 1) s += __shfl_xor_sync(0xffffffffu, s, o);
        const float mu = s * (1.0f / HDIM);
        float d0 = x0 - mu, d1 = x1 - mu, d2 = (lane < 8) ? (x2 - mu) : 0.f;
        float vs = d0 * d0 + d1 * d1 + d2 * d2;
#pragma unroll
        for (int o = 16; o; o >>= 1) vs += __shfl_xor_sync(0xffffffffu, vs, o);
        const float inv = rsqrtf(vs * (1.0f / HDIM) + LN_EPS);
        qt[obase + lane]      = (d0 * inv * qg[lane]      + qb[lane])      * SCALE;
        qt[obase + lane + 32] = (d1 * inv * qg[lane + 32] + qb[lane + 32]) * SCALE;
        if (lane < 8)
            qt[obase + lane + 64] = (d2 * inv * qg[lane + 64] + qb[lane + 64]) * SCALE;
    }
    // ---- k layernorm ----
    {
        float x0 = k[lane], x1 = k[lane + 32];
        float x2 = (lane < 8) ? k[lane + 64] : 0.f;
        float s = x0 + x1 + x2;
#pragma unroll
        for (int o = 16; o; o >>= 1) s += __shfl_xor_sync(0xffffffffu, s, o);
        const float mu = s * (1.0f / HDIM);
        float d0 = x0 - mu, d1 = x1 - mu, d2 = (lane < 8) ? (x2 - mu) : 0.f;
        float vs = d0 * d0 + d1 * d1 + d2 * d2;
#pragma unroll
        for (int o = 16; o; o >>= 1) vs += __shfl_xor_sync(0xffffffffu, vs, o);
        const float inv = rsqrtf(vs * (1.0f / HDIM) + LN_EPS);
        kt[obase + lane]      = d0 * inv * kg[lane]      + kb[lane];
        kt[obase + lane + 32] = d1 * inv * kg[lane + 32] + kb[lane + 32];
        if (lane < 8)
            kt[obase + lane + 64] = d2 * inv * kg[lane + 64] + kb[lane + 64];
    }
    // ---- v copy ----
    vt[obase + lane]      = v[lane];
    vt[obase + lane + 32] = v[lane + 32];
    if (lane < 8) vt[obase + lane + 64] = v[lane + 64];
}

// ---------------- row softmax over 2048 cols ----------------
__global__ __launch_bounds__(256)
void softmax_rows(float* __restrict__ S)
{
    __shared__ float red[8];
    float* p = S + (size_t)blockIdx.x * SEQ;
    const int tid = threadIdx.x;
    const int w = tid >> 5, l = tid & 31;

    float vals[8];
    float m = -FLT_MAX;
#pragma unroll
    for (int i = 0; i < 8; i++) {
        vals[i] = p[tid + i * 256];
        m = fmaxf(m, vals[i]);
    }
#pragma unroll
    for (int o = 16; o; o >>= 1) m = fmaxf(m, __shfl_xor_sync(0xffffffffu, m, o));
    if (l == 0) red[w] = m;
    __syncthreads();
    m = red[l & 7];
#pragma unroll
    for (int o = 4; o; o >>= 1) m = fmaxf(m, __shfl_xor_sync(0xffffffffu, m, o));

    float s = 0.f;
#pragma unroll
    for (int i = 0; i < 8; i++) {
        vals[i] = __expf(vals[i] - m);
        s += vals[i];
    }
#pragma unroll
    for (int o = 16; o; o >>= 1) s += __shfl_xor_sync(0xffffffffu, s, o);
    __syncthreads();
    if (l == 0) red[w] = s;
    __syncthreads();
    s = red[l & 7];
#pragma unroll
    for (int o = 4; o; o >>= 1) s += __shfl_xor_sync(0xffffffffu, s, o);

    const float inv = 1.0f / s;
#pragma unroll
    for (int i = 0; i < 8; i++) p[tid + i * 256] = vals[i] * inv;
}

// ---------------- O = P @ V, written directly as [B,N,H*D] ----------------
__global__ __launch_bounds__(576)
void pv_gemm(const float* __restrict__ S, const float* __restrict__ vt,
             float* __restrict__ out)
{
    __shared__ float Ss[64][65];
    __shared__ float Vs[64][HDIM];

    const int bh = blockIdx.y;
    const int m0 = blockIdx.x * 64;
    const int d  = threadIdx.x;      // 0..71
    const int my = threadIdx.y;      // 0..7
    const int tid = my * HDIM + d;   // 0..575

    const float* Sp = S + ((size_t)bh * SEQ + m0) * SEQ;
    const float* Vp = vt + (size_t)bh * SEQ * HDIM;

    float acc[8];
#pragma unroll
    for (int i = 0; i < 8; i++) acc[i] = 0.f;

    for (int k0 = 0; k0 < SEQ; k0 += 64) {
        __syncthreads();
        for (int idx = tid; idx < 64 * 64; idx += 576)
            Ss[idx >> 6][idx & 63] = Sp[(size_t)(idx >> 6) * SEQ + k0 + (idx & 63)];
        for (int idx = tid; idx < 64 * HDIM; idx += 576)
            Vs[idx / HDIM][idx % HDIM] = Vp[(size_t)(k0 + idx / HDIM) * HDIM + idx % HDIM];
        __syncthreads();
#pragma unroll 4
        for (int kk = 0; kk < 64; kk++) {
            const float v = Vs[kk][d];
#pragma unroll
            for (int i = 0; i < 8; i++) acc[i] += Ss[my + 8 * i][kk] * v;
        }
    }

    const int b = bh / NHEAD, h = bh % NHEAD;
#pragma unroll
    for (int i = 0; i < 8; i++) {
        const int n = m0 + my + 8 * i;
        out[((size_t)(b * SEQ + n)) * DIM + h * HDIM + d] = acc[i];
    }
}

// ---------------- host launcher ----------------
extern "C" void kernel_launch(void* const* d_in, const int* in_sizes, int n_in,
                              void* d_out, int out_size)
{
    const float* x      = (const float*)d_in[0];
    const float* w_qkv  = (const float*)d_in[1];
    const float* b_qkv  = (const float*)d_in[2];
    const float* q_g    = (const float*)d_in[3];
    const float* q_b    = (const float*)d_in[4];
    const float* k_g    = (const float*)d_in[5];
    const float* k_b    = (const float*)d_in[6];
    const float* w_proj = (const float*)d_in[7];
    const float* b_proj = (const float*)d_in[8];
    float* out = (float*)d_out;

    void *p_qkv, *p_qt, *p_kt, *p_vt, *p_S, *p_ao;
    cudaGetSymbolAddress(&p_qkv, g_qkv);
    cudaGetSymbolAddress(&p_qt,  g_qt);
    cudaGetSymbolAddress(&p_kt,  g_kt);
    cudaGetSymbolAddress(&p_vt,  g_vt);
    cudaGetSymbolAddress(&p_S,   g_S);
    cudaGetSymbolAddress(&p_ao,  g_ao);

    // 1) QKV GEMM: [4096,3456] = x[4096,1152] @ w_qkv[3456,1152]^T + b
    sgemm_nt<<<dim3(O3 / 128, MROWS / 128, 1), 256>>>(
        x, w_qkv, b_qkv, (float*)p_qkv, MROWS, O3, DIM, 0, 0, 0);

    // 2) LayerNorm q/k (+SCALE on q), transpose to [B,H,N,D]
    ln_split<<<(BATCH * SEQ * NHEAD) / 8, 256>>>(
        (const float*)p_qkv, q_g, q_b, k_g, k_b,
        (float*)p_qt, (float*)p_kt, (float*)p_vt);

    // 3) S = q @ k^T, batched over 32 (b,h)
    sgemm_nt<<<dim3(SEQ / 128, SEQ / 128, BH), 256>>>(
        (const float*)p_qt, (const float*)p_kt, nullptr, (float*)p_S,
        SEQ, SEQ, HDIM,
        (long long)SEQ * HDIM, (long long)SEQ * HDIM, (long long)SEQ * SEQ);

    // 4) softmax over rows
    softmax_rows<<<BH * SEQ, 256>>>((float*)p_S);

    // 5) O = P @ V  -> [B,N,H*D]
    pv_gemm<<<dim3(SEQ / 64, BH), dim3(HDIM, 8)>>>(
        (const float*)p_S, (const float*)p_vt, (float*)p_ao);

    // 6) projection: out = ao @ w_proj^T + b_proj
    sgemm_nt<<<dim3(DIM / 128, MROWS / 128, 1), 256>>>(
        (const float*)p_ao, w_proj, b_proj, out, MROWS, DIM, DIM, 0, 0, 0);
}

// round 3
// speedup vs baseline: 3.1714x; 3.1714x over previous
#include <cuda_runtime.h>
#include <cuda_bf16.h>
#include <cstdint>
#include <math.h>
#include <float.h>

#define BATCH 2
#define SEQ   2048
#define DIM   1152
#define NHEAD 16
#define HDIM  72
#define HDIMP 96
#define O3    (3 * DIM)         // 3456
#define MROWS (BATCH * SEQ)     // 4096
#define BH    (BATCH * NHEAD)   // 32
#define SCALE 0.1178511301977579f
#define LN_EPS 1e-5f

// ---------------- scratch ----------------
__device__ float g_qkv[(size_t)MROWS * O3];
__device__ float g_qt[(size_t)BH * SEQ * HDIMP];          // [bh][n][96]
__device__ float g_kt[(size_t)BH * SEQ * HDIMP];          // [bh][n][96]
__device__ float g_vtT[(size_t)BH * HDIMP * SEQ];         // [bh][96][2048] (transposed, pad rows stay 0)
__device__ float g_S [(size_t)BH * SEQ * SEQ];
__device__ float g_ao[(size_t)MROWS * DIM];

__device__ __forceinline__ float totf32(float x) {
    float r; asm("cvt.rna.tf32.f32 %0, %1;" : "=f"(r) : "f"(x)); return r;
}

__device__ __forceinline__ void mma8(float c[4], const uint32_t a[4], const uint32_t b[2]) {
    asm volatile(
        "mma.sync.aligned.m16n8k8.row.col.f32.tf32.tf32.f32 "
        "{%0,%1,%2,%3}, {%4,%5,%6,%7}, {%8,%9}, {%0,%1,%2,%3};"
        : "+f"(c[0]), "+f"(c[1]), "+f"(c[2]), "+f"(c[3])
        : "r"(a[0]), "r"(a[1]), "r"(a[2]), "r"(a[3]), "r"(b[0]), "r"(b[1]));
}

// ================= tf32 mma.sync GEMM =================
// C[z][m, 0..BN) = A[z][m, :K] @ B[z][n, :K]^T (+bias), block tile 128 x BN, K-chunk 32.
// 256 threads = 8 warps in 2(M) x 4(N); warp tile 64 x (BN/4).
// Store guarded to col < NSTORE (for PV head-dim 72).
template<int BN, int NSTORE>
__global__ __launch_bounds__(256)
void tmma_gemm(const float* __restrict__ A, const float* __restrict__ B,
               const float* __restrict__ bias, float* __restrict__ C,
               int K, int lda, int ldb, int ldc,
               long long sA, long long sB, long long sCo, long long sCi, int cdiv)
{
    extern __shared__ float sm[];
    constexpr int NT = BN / 32;          // n-tiles per warp
    constexpr int WN = BN / 4;           // warp n extent
    constexpr int AW = 36;               // padded word stride
    constexpr int ABUF = 128 * AW;       // words
    constexpr int BBUF = BN * AW;
    constexpr int BUF = ABUF + BBUF;
    constexpr int BITER = BN / 32;       // B g2s iterations

    const int tid = threadIdx.x, wid = tid >> 5, lane = tid & 31;
    const int g = lane >> 2, tig = lane & 3;
    const int wm = wid & 1, wn = wid >> 1;
    const int m0 = blockIdx.y * 128;
    const int n0 = blockIdx.x * BN;
    const int z = blockIdx.z;

    A += (long long)z * sA;
    B += (long long)z * sB;
    C += (long long)(z / cdiv) * sCo + (long long)(z % cdiv) * sCi;

    const int arow = tid >> 3;           // 0..31
    const int ac4  = (tid & 7) * 4;      // 0,4,...,28

    float acc[4][NT][4];
#pragma unroll
    for (int mt = 0; mt < 4; mt++)
#pragma unroll
        for (int nt = 0; nt < NT; nt++)
#pragma unroll
            for (int j = 0; j < 4; j++) acc[mt][nt][j] = 0.f;

    const int nch = K / 32;

    // ---- g2s into buffer 0 ----
    {
        float* As = sm;
        float* Bs = sm + ABUF;
#pragma unroll
        for (int i = 0; i < 4; i++) {
            int r = arow + i * 32;
            float4 v = *(const float4*)(A + (size_t)(m0 + r) * lda + ac4);
            *(float4*)(As + r * AW + ac4) =
                make_float4(totf32(v.x), totf32(v.y), totf32(v.z), totf32(v.w));
        }
#pragma unroll
        for (int i = 0; i < BITER; i++) {
            int r = arow + i * 32;
            float4 v = *(const float4*)(B + (size_t)(n0 + r) * ldb + ac4);
            *(float4*)(Bs + r * AW + ac4) =
                make_float4(totf32(v.x), totf32(v.y), totf32(v.z), totf32(v.w));
        }
    }
    __syncthreads();

    for (int c = 0; c < nch; c++) {
        const int cur = c & 1;
        float4 av[4], bv[BITER];
        const bool pre = (c + 1 < nch);
        if (pre) {
            const int k0 = (c + 1) * 32;
#pragma unroll
            for (int i = 0; i < 4; i++)
                av[i] = *(const float4*)(A + (size_t)(m0 + arow + i * 32) * lda + k0 + ac4);
#pragma unroll
            for (int i = 0; i < BITER; i++)
                bv[i] = *(const float4*)(B + (size_t)(n0 + arow + i * 32) * ldb + k0 + ac4);
        }

        // ---- compute on current buffer ----
        {
            const uint32_t* As = (const uint32_t*)(sm + cur * BUF);
            const uint32_t* Bs = As + ABUF;
#pragma unroll
            for (int ks = 0; ks < 4; ks++) {
                const int kk = ks * 8;
                uint32_t af[4][4];
#pragma unroll
                for (int mt = 0; mt < 4; mt++) {
                    const int mr = wm * 64 + mt * 16;
                    af[mt][0] = As[(mr + g) * AW + kk + tig];
                    af[mt][1] = As[(mr + g + 8) * AW + kk + tig];
                    af[mt][2] = As[(mr + g) * AW + kk + tig + 4];
                    af[mt][3] = As[(mr + g + 8) * AW + kk + tig + 4];
                }
                uint32_t bf[NT][2];
#pragma unroll
                for (int nt = 0; nt < NT; nt++) {
                    const int nr = wn * WN + nt * 8;
                    bf[nt][0] = Bs[(nr + g) * AW + kk + tig];
                    bf[nt][1] = Bs[(nr + g) * AW + kk + tig + 4];
                }
#pragma unroll
                for (int mt = 0; mt < 4; mt++)
#pragma unroll
                    for (int nt = 0; nt < NT; nt++)
                        mma8(acc[mt][nt], af[mt], bf[nt]);
            }
        }

        if (pre) {
            float* As = sm + (cur ^ 1) * BUF;
            float* Bs = As + ABUF;
#pragma unroll
            for (int i = 0; i < 4; i++)
                *(float4*)(As + (arow + i * 32) * AW + ac4) =
                    make_float4(totf32(av[i].x), totf32(av[i].y), totf32(av[i].z), totf32(av[i].w));
#pragma unroll
            for (int i = 0; i < BITER; i++)
                *(float4*)(Bs + (arow + i * 32) * AW + ac4) =
                    make_float4(totf32(bv[i].x), totf32(bv[i].y), totf32(bv[i].z), totf32(bv[i].w));
        }
        __syncthreads();
    }

    // ---- epilogue ----
#pragma unroll
    for (int mt = 0; mt < 4; mt++) {
        const int r0 = m0 + wm * 64 + mt * 16 + g;
#pragma unroll
        for (int nt = 0; nt < NT; nt++) {
            const int col = wn * WN + nt * 8 + 2 * tig;   // within block tile
            if (col < NSTORE) {
                float bx = 0.f, by = 0.f;
                if (bias) { bx = bias[n0 + col]; by = bias[n0 + col + 1]; }
                *(float2*)(C + (size_t)r0 * ldc + n0 + col) =
                    make_float2(acc[mt][nt][0] + bx, acc[mt][nt][1] + by);
                *(float2*)(C + (size_t)(r0 + 8) * ldc + n0 + col) =
                    make_float2(acc[mt][nt][2] + bx, acc[mt][nt][3] + by);
            }
        }
    }
}

// ------------- LayerNorm(q,k) + SCALE + transpose; V written transposed --------
__global__ __launch_bounds__(256)
void ln_split(const float* __restrict__ qkv,
              const float* __restrict__ qg, const float* __restrict__ qb,
              const float* __restrict__ kg, const float* __restrict__ kb,
              float* __restrict__ qt, float* __restrict__ kt, float* __restrict__ vtT)
{
    int task = blockIdx.x * 8 + (threadIdx.x >> 5);
    if (task >= BATCH * SEQ * NHEAD) return;
    const int lane = threadIdx.x & 31;
    const int h = task % NHEAD;
    const int n = (task / NHEAD) % SEQ;
    const int b = task / (NHEAD * SEQ);
    const int bh = b * NHEAD + h;

    const size_t ibase = ((size_t)(b * SEQ + n) * 3) * DIM + h * HDIM;
    const size_t oqk = ((size_t)bh * SEQ + n) * HDIMP;

    const float* q = qkv + ibase;
    const float* k = qkv + ibase + DIM;
    const float* v = qkv + ibase + 2 * DIM;

    {
        float x0 = q[lane], x1 = q[lane + 32];
        float x2 = (lane < 8) ? q[lane + 64] : 0.f;
        float s = x0 + x1 + x2;
#pragma unroll
        for (int o = 16; o; o >>= 1) s += __shfl_xor_sync(0xffffffffu, s, o);
        const float mu = s * (1.0f / HDIM);
        float d0 = x0 - mu, d1 = x1 - mu, d2 = (lane < 8) ? (x2 - mu) : 0.f;
        float vs = d0 * d0 + d1 * d1 + d2 * d2;
#pragma unroll
        for (int o = 16; o; o >>= 1) vs += __shfl_xor_sync(0xffffffffu, vs, o);
        const float inv = rsqrtf(vs * (1.0f / HDIM) + LN_EPS);
        qt[oqk + lane]      = (d0 * inv * qg[lane]      + qb[lane])      * SCALE;
        qt[oqk + lane + 32] = (d1 * inv * qg[lane + 32] + qb[lane + 32]) * SCALE;
        qt[oqk + lane + 64] = (lane < 8) ? (d2 * inv * qg[lane + 64] + qb[lane + 64]) * SCALE : 0.f;
    }
    {
        float x0 = k[lane], x1 = k[lane + 32];
        float x2 = (lane < 8) ? k[lane + 64] : 0.f;
        float s = x0 + x1 + x2;
#pragma unroll
        for (int o = 16; o; o >>= 1) s += __shfl_xor_sync(0xffffffffu, s, o);
        const float mu = s * (1.0f / HDIM);
        float d0 = x0 - mu, d1 = x1 - mu, d2 = (lane < 8) ? (x2 - mu) : 0.f;
        float vs = d0 * d0 + d1 * d1 + d2 * d2;
#pragma unroll
        for (int o = 16; o; o >>= 1) vs += __shfl_xor_sync(0xffffffffu, vs, o);
        const float inv = rsqrtf(vs * (1.0f / HDIM) + LN_EPS);
        kt[oqk + lane]      = d0 * inv * kg[lane]      + kb[lane];
        kt[oqk + lane + 32] = d1 * inv * kg[lane + 32] + kb[lane + 32];
        kt[oqk + lane + 64] = (lane < 8) ? (d2 * inv * kg[lane + 64] + kb[lane + 64]) : 0.f;
    }
    // V transposed: vtT[bh][d][n]  (rows 72..95 never written -> stay zero)
    {
        float* vb = vtT + (size_t)bh * HDIMP * SEQ + n;
        vb[(size_t)lane * SEQ]        = v[lane];
        vb[(size_t)(lane + 32) * SEQ] = v[lane + 32];
        if (lane < 8) vb[(size_t)(lane + 64) * SEQ] = v[lane + 64];
    }
}

// ---------------- row softmax over 2048 cols ----------------
__global__ __launch_bounds__(256)
void softmax_rows(float* __restrict__ S)
{
    __shared__ float red[8];
    float* p = S + (size_t)blockIdx.x * SEQ;
    const int tid = threadIdx.x;
    const int w = tid >> 5, l = tid & 31;

    float vals[8];
    float m = -FLT_MAX;
#pragma unroll
    for (int i = 0; i < 8; i++) {
        vals[i] = p[tid + i * 256];
        m = fmaxf(m, vals[i]);
    }
#pragma unroll
    for (int o = 16; o; o >>= 1) m = fmaxf(m, __shfl_xor_sync(0xffffffffu, m, o));
    if (l == 0) red[w] = m;
    __syncthreads();
    m = red[l & 7];
#pragma unroll
    for (int o = 4; o; o >>= 1) m = fmaxf(m, __shfl_xor_sync(0xffffffffu, m, o));

    float s = 0.f;
#pragma unroll
    for (int i = 0; i < 8; i++) {
        vals[i] = __expf(vals[i] - m);
        s += vals[i];
    }
#pragma unroll
    for (int o = 16; o; o >>= 1) s += __shfl_xor_sync(0xffffffffu, s, o);
    __syncthreads();
    if (l == 0) red[w] = s;
    __syncthreads();
    s = red[l & 7];
#pragma unroll
    for (int o = 4; o; o >>= 1) s += __shfl_xor_sync(0xffffffffu, s, o);

    const float inv = 1.0f / s;
#pragma unroll
    for (int i = 0; i < 8; i++) p[tid + i * 256] = vals[i] * inv;
}

// ---------------- host launcher ----------------
extern "C" void kernel_launch(void* const* d_in, const int* in_sizes, int n_in,
                              void* d_out, int out_size)
{
    const float* x      = (const float*)d_in[0];
    const float* w_qkv  = (const float*)d_in[1];
    const float* b_qkv  = (const float*)d_in[2];
    const float* q_g    = (const float*)d_in[3];
    const float* q_b    = (const float*)d_in[4];
    const float* k_g    = (const float*)d_in[5];
    const float* k_b    = (const float*)d_in[6];
    const float* w_proj = (const float*)d_in[7];
    const float* b_proj = (const float*)d_in[8];
    float* out = (float*)d_out;

    void *p_qkv, *p_qt, *p_kt, *p_vtT, *p_S, *p_ao;
    cudaGetSymbolAddress(&p_qkv, g_qkv);
    cudaGetSymbolAddress(&p_qt,  g_qt);
    cudaGetSymbolAddress(&p_kt,  g_kt);
    cudaGetSymbolAddress(&p_vtT, g_vtT);
    cudaGetSymbolAddress(&p_S,   g_S);
    cudaGetSymbolAddress(&p_ao,  g_ao);

    // dynamic smem sizes: 2 * (128 + BN) * 36 words * 4B
    const int smem128 = 2 * (128 + 128) * 36 * 4;   // 73728
    const int smem96  = 2 * (128 + 96)  * 36 * 4;   // 64512
    cudaFuncSetAttribute(tmma_gemm<128, 128>, cudaFuncAttributeMaxDynamicSharedMemorySize, smem128);
    cudaFuncSetAttribute(tmma_gemm<96, 72>,   cudaFuncAttributeMaxDynamicSharedMemorySize, smem96);

    // 1) QKV: [4096,3456] = x @ w_qkv^T + b
    tmma_gemm<128, 128><<<dim3(O3 / 128, MROWS / 128, 1), 256, smem128>>>(
        x, w_qkv, b_qkv, (float*)p_qkv,
        DIM, DIM, DIM, O3, 0, 0, 0, 0, 1);

    // 2) LayerNorm + transpose (+V transpose)
    ln_split<<<(BATCH * SEQ * NHEAD) / 8, 256>>>(
        (const float*)p_qkv, q_g, q_b, k_g, k_b,
        (float*)p_qt, (float*)p_kt, (float*)p_vtT);

    // 3) S = q @ k^T (K padded to 96), batched over 32 heads
    tmma_gemm<128, 128><<<dim3(SEQ / 128, SEQ / 128, BH), 256, smem128>>>(
        (const float*)p_qt, (const float*)p_kt, nullptr, (float*)p_S,
        HDIMP, HDIMP, HDIMP, SEQ,
        (long long)SEQ * HDIMP, (long long)SEQ * HDIMP,
        (long long)SEQ * SEQ, 0, 1);

    // 4) softmax
    softmax_rows<<<BH * SEQ, 256>>>((float*)p_S);

    // 5) O = P @ V^T  (B = vtT[bh][96][2048]) -> ao[B,N,1152]
    tmma_gemm<96, 72><<<dim3(1, SEQ / 128, BH), 256, smem96>>>(
        (const float*)p_S, (const float*)p_vtT, nullptr, (float*)p_ao,
        SEQ, SEQ, SEQ, DIM,
        (long long)SEQ * SEQ, (long long)HDIMP * SEQ,
        (long long)SEQ * DIM, (long long)HDIM, NHEAD);

    // 6) projection: out = ao @ w_proj^T + b_proj
    tmma_gemm<128, 128><<<dim3(DIM / 128, MROWS / 128, 1), 256, smem128>>>(
        (const float*)p_ao, w_proj, b_proj, out,
        DIM, DIM, DIM, DIM, 0, 0, 0, 0, 1);
}

// round 4
// speedup vs baseline: 4.8788x; 1.5384x over previous
#include <cuda_runtime.h>
#include <cuda_fp16.h>
#include <cstdint>
#include <math.h>
#include <float.h>

#define BATCH 2
#define SEQ   2048
#define DIM   1152
#define NHEAD 16
#define HDIM  72
#define HDIMP 96
#define O3    (3 * DIM)
#define MROWS (BATCH * SEQ)     // 4096
#define BH    (BATCH * NHEAD)   // 32
#define SCALE 0.1178511301977579f
#define LN_EPS 1e-5f

// ---------------- scratch ----------------
__device__ float  g_qkv[(size_t)MROWS * O3];               // fp32 [B,N,3,H,D]
__device__ __half g_qt[(size_t)BH * SEQ * HDIMP];          // [bh][n][96]
__device__ __half g_kt[(size_t)BH * SEQ * HDIMP];
__device__ __half g_vtT[(size_t)BH * HDIMP * SEQ];         // [bh][96][2048], pad rows stay 0
__device__ __half g_S [(size_t)BH * SEQ * SEQ];            // 268 MB
__device__ __half g_ao[(size_t)MROWS * DIM];

__device__ __forceinline__ uint32_t packh2(float x, float y) {
    __half2 h = __floats2half2_rn(x, y);
    return *(uint32_t*)&h;
}

__device__ __forceinline__ void mma16(float c[4], const uint32_t a[4], const uint32_t b[2]) {
    asm volatile(
        "mma.sync.aligned.m16n8k16.row.col.f32.f16.f16.f32 "
        "{%0,%1,%2,%3}, {%4,%5,%6,%7}, {%8,%9}, {%0,%1,%2,%3};"
        : "+f"(c[0]), "+f"(c[1]), "+f"(c[2]), "+f"(c[3])
        : "r"(a[0]), "r"(a[1]), "r"(a[2]), "r"(a[3]), "r"(b[0]), "r"(b[1]));
}

// ================= fp16 mma.sync GEMM =================
// C[z][m, 0..BN) = A[z][m,:K] @ B[z][n,:K]^T (+bias). Block 128 x BN, K-chunk 32.
// 256 thr = 8 warps, 2(M) x 4(N); warp tile 64 x (BN/4). fp32 accumulate.
// A16/B16: operand already fp16 in gmem. C16: store fp16. Cols guarded < NSTORE.
template<int BN, int NSTORE, bool A16, bool B16, bool C16>
__global__ __launch_bounds__(256)
void hgemm(const void* __restrict__ A_, const void* __restrict__ B_,
           const float* __restrict__ bias, void* __restrict__ C_,
           int K, int lda, int ldb, int ldc,
           long long sA, long long sB, long long sCo, long long sCi, int cdiv)
{
    extern __shared__ __half smh[];
    constexpr int PAD = 40;               // halves per row (K-chunk 32 + pad 8)
    constexpr int ABUF = 128 * PAD;
    constexpr int BBUF = BN * PAD;
    constexpr int BUF = ABUF + BBUF;
    constexpr int IA = 4, IB = BN / 32;
    constexpr int WN = BN / 4, NT = BN / 32;

    const int tid = threadIdx.x, wid = tid >> 5, lane = tid & 31;
    const int g = lane >> 2, tig = lane & 3;
    const int wm = wid & 1, wn = wid >> 1;
    const int m0 = blockIdx.y * 128;
    const int n0 = blockIdx.x * BN;
    const int z = blockIdx.z;
    const int arow = tid >> 3;            // 0..31
    const int ac4 = (tid & 7) * 4;

    const float*  Af = (const float*)A_  + (A16 ? 0 : (long long)z * sA);
    const __half* Ah = (const __half*)A_ + (A16 ? (long long)z * sA : 0);
    const float*  Bf = (const float*)B_  + (B16 ? 0 : (long long)z * sB);
    const __half* Bh = (const __half*)B_ + (B16 ? (long long)z * sB : 0);
    const long long coff = (long long)(z / cdiv) * sCo + (long long)(z % cdiv) * sCi;
    float*  Cf = (float*)C_  + (C16 ? 0 : coff);
    __half* Ch = (__half*)C_ + (C16 ? coff : 0);

    float acc[4][NT][4];
#pragma unroll
    for (int mt = 0; mt < 4; mt++)
#pragma unroll
        for (int nt = 0; nt < NT; nt++)
#pragma unroll
            for (int j = 0; j < 4; j++) acc[mt][nt][j] = 0.f;

    const int nch = K / 32;

    // ---- fill buffer 0 ----
    {
        __half* As = smh;
        __half* Bs = smh + ABUF;
#pragma unroll
        for (int i = 0; i < IA; i++) {
            int r = arow + i * 32;
            __half* dst = As + r * PAD + ac4;
            if (A16) *(uint2*)dst = *(const uint2*)(Ah + (size_t)(m0 + r) * lda + ac4);
            else {
                float4 v = *(const float4*)(Af + (size_t)(m0 + r) * lda + ac4);
                *(uint2*)dst = make_uint2(packh2(v.x, v.y), packh2(v.z, v.w));
            }
        }
#pragma unroll
        for (int i = 0; i < IB; i++) {
            int r = arow + i * 32;
            __half* dst = Bs + r * PAD + ac4;
            if (B16) *(uint2*)dst = *(const uint2*)(Bh + (size_t)(n0 + r) * ldb + ac4);
            else {
                float4 v = *(const float4*)(Bf + (size_t)(n0 + r) * ldb + ac4);
                *(uint2*)dst = make_uint2(packh2(v.x, v.y), packh2(v.z, v.w));
            }
        }
    }
    __syncthreads();

    for (int c = 0; c < nch; c++) {
        const int cur = c & 1;
        const bool pre = (c + 1 < nch);
        float4 pav[IA], pbv[IB];
        uint2  hav[IA], hbv[IB];
        if (pre) {
            const int k0 = (c + 1) * 32;
#pragma unroll
            for (int i = 0; i < IA; i++) {
                if (A16) hav[i] = *(const uint2*)(Ah + (size_t)(m0 + arow + i * 32) * lda + k0 + ac4);
                else     pav[i] = *(const float4*)(Af + (size_t)(m0 + arow + i * 32) * lda + k0 + ac4);
            }
#pragma unroll
            for (int i = 0; i < IB; i++) {
                if (B16) hbv[i] = *(const uint2*)(Bh + (size_t)(n0 + arow + i * 32) * ldb + k0 + ac4);
                else     pbv[i] = *(const float4*)(Bf + (size_t)(n0 + arow + i * 32) * ldb + k0 + ac4);
            }
        }

        // ---- compute current buffer ----
        {
            const __half* As = smh + cur * BUF;
            const __half* Bs = As + ABUF;
#pragma unroll
            for (int ks = 0; ks < 2; ks++) {
                const int kk = ks * 16;
                uint32_t af[4][4];
#pragma unroll
                for (int mt = 0; mt < 4; mt++) {
                    const __half* ap = As + (wm * 64 + mt * 16 + g) * PAD + kk + 2 * tig;
                    af[mt][0] = *(const uint32_t*)ap;
                    af[mt][1] = *(const uint32_t*)(ap + 8 * PAD);
                    af[mt][2] = *(const uint32_t*)(ap + 8);
                    af[mt][3] = *(const uint32_t*)(ap + 8 * PAD + 8);
                }
                uint32_t bf[NT][2];
#pragma unroll
                for (int nt = 0; nt < NT; nt++) {
                    const __half* bp = Bs + (wn * WN + nt * 8 + g) * PAD + kk + 2 * tig;
                    bf[nt][0] = *(const uint32_t*)bp;
                    bf[nt][1] = *(const uint32_t*)(bp + 8);
                }
#pragma unroll
                for (int mt = 0; mt < 4; mt++)
#pragma unroll
                    for (int nt = 0; nt < NT; nt++)
                        mma16(acc[mt][nt], af[mt], bf[nt]);
            }
        }

        if (pre) {
            __half* As = smh + (cur ^ 1) * BUF;
            __half* Bs = As + ABUF;
#pragma unroll
            for (int i = 0; i < IA; i++) {
                __half* dst = As + (arow + i * 32) * PAD + ac4;
                if (A16) *(uint2*)dst = hav[i];
                else     *(uint2*)dst = make_uint2(packh2(pav[i].x, pav[i].y), packh2(pav[i].z, pav[i].w));
            }
#pragma unroll
            for (int i = 0; i < IB; i++) {
                __half* dst = Bs + (arow + i * 32) * PAD + ac4;
                if (B16) *(uint2*)dst = hbv[i];
                else     *(uint2*)dst = make_uint2(packh2(pbv[i].x, pbv[i].y), packh2(pbv[i].z, pbv[i].w));
            }
        }
        __syncthreads();
    }

    // ---- epilogue ----
#pragma unroll
    for (int mt = 0; mt < 4; mt++) {
        const int r0 = m0 + wm * 64 + mt * 16 + g;
#pragma unroll
        for (int nt = 0; nt < NT; nt++) {
            const int col = wn * WN + nt * 8 + 2 * tig;
            if (col < NSTORE) {
                float bx = 0.f, by = 0.f;
                if (bias) { bx = bias[n0 + col]; by = bias[n0 + col + 1]; }
                const float v0 = acc[mt][nt][0] + bx, v1 = acc[mt][nt][1] + by;
                const float v2 = acc[mt][nt][2] + bx, v3 = acc[mt][nt][3] + by;
                if (C16) {
                    *(__half2*)(Ch + (size_t)r0 * ldc + n0 + col)       = __floats2half2_rn(v0, v1);
                    *(__half2*)(Ch + (size_t)(r0 + 8) * ldc + n0 + col) = __floats2half2_rn(v2, v3);
                } else {
                    *(float2*)(Cf + (size_t)r0 * ldc + n0 + col)        = make_float2(v0, v1);
                    *(float2*)(Cf + (size_t)(r0 + 8) * ldc + n0 + col)  = make_float2(v2, v3);
                }
            }
        }
    }
}

// ------------- LayerNorm(q,k) + SCALE + transpose -> fp16; V transposed fp16 ----
__global__ __launch_bounds__(256)
void ln_split(const float* __restrict__ qkv,
              const float* __restrict__ qg, const float* __restrict__ qb,
              const float* __restrict__ kg, const float* __restrict__ kb,
              __half* __restrict__ qt, __half* __restrict__ kt, __half* __restrict__ vtT)
{
    int task = blockIdx.x * 8 + (threadIdx.x >> 5);
    if (task >= BATCH * SEQ * NHEAD) return;
    const int lane = threadIdx.x & 31;
    const int h = task % NHEAD;
    const int n = (task / NHEAD) % SEQ;
    const int b = task / (NHEAD * SEQ);
    const int bh = b * NHEAD + h;

    const size_t ibase = ((size_t)(b * SEQ + n) * 3) * DIM + h * HDIM;
    const size_t oqk = ((size_t)bh * SEQ + n) * HDIMP;

    const float* q = qkv + ibase;
    const float* k = qkv + ibase + DIM;
    const float* v = qkv + ibase + 2 * DIM;

    {
        float x0 = q[lane], x1 = q[lane + 32];
        float x2 = (lane < 8) ? q[lane + 64] : 0.f;
        float s = x0 + x1 + x2;
#pragma unroll
        for (int o = 16; o; o >>= 1) s += __shfl_xor_sync(0xffffffffu, s, o);
        const float mu = s * (1.0f / HDIM);
        float d0 = x0 - mu, d1 = x1 - mu, d2 = (lane < 8) ? (x2 - mu) : 0.f;
        float vs = d0 * d0 + d1 * d1 + d2 * d2;
#pragma unroll
        for (int o = 16; o; o >>= 1) vs += __shfl_xor_sync(0xffffffffu, vs, o);
        const float inv = rsqrtf(vs * (1.0f / HDIM) + LN_EPS);
        qt[oqk + lane]      = __float2half_rn((d0 * inv * qg[lane]      + qb[lane])      * SCALE);
        qt[oqk + lane + 32] = __float2half_rn((d1 * inv * qg[lane + 32] + qb[lane + 32]) * SCALE);
        qt[oqk + lane + 64] = __float2half_rn((lane < 8) ? (d2 * inv * qg[lane + 64] + qb[lane + 64]) * SCALE : 0.f);
    }
    {
        float x0 = k[lane], x1 = k[lane + 32];
        float x2 = (lane < 8) ? k[lane + 64] : 0.f;
        float s = x0 + x1 + x2;
#pragma unroll
        for (int o = 16; o; o >>= 1) s += __shfl_xor_sync(0xffffffffu, s, o);
        const float mu = s * (1.0f / HDIM);
        float d0 = x0 - mu, d1 = x1 - mu, d2 = (lane < 8) ? (x2 - mu) : 0.f;
        float vs = d0 * d0 + d1 * d1 + d2 * d2;
#pragma unroll
        for (int o = 16; o; o >>= 1) vs += __shfl_xor_sync(0xffffffffu, vs, o);
        const float inv = rsqrtf(vs * (1.0f / HDIM) + LN_EPS);
        kt[oqk + lane]      = __float2half_rn(d0 * inv * kg[lane]      + kb[lane]);
        kt[oqk + lane + 32] = __float2half_rn(d1 * inv * kg[lane + 32] + kb[lane + 32]);
        kt[oqk + lane + 64] = __float2half_rn((lane < 8) ? (d2 * inv * kg[lane + 64] + kb[lane + 64]) : 0.f);
    }
    {
        __half* vb = vtT + (size_t)bh * HDIMP * SEQ + n;
        vb[(size_t)lane * SEQ]        = __float2half_rn(v[lane]);
        vb[(size_t)(lane + 32) * SEQ] = __float2half_rn(v[lane + 32]);
        if (lane < 8) vb[(size_t)(lane + 64) * SEQ] = __float2half_rn(v[lane + 64]);
    }
}

// ---------------- fp16 row softmax over 2048 cols ----------------
__global__ __launch_bounds__(256)
void softmax_rows_h(__half2* __restrict__ S)
{
    __shared__ float red[8];
    __half2* p = S + (size_t)blockIdx.x * (SEQ / 2);
    const int tid = threadIdx.x;
    const int w = tid >> 5, l = tid & 31;

    float2 vals[4];
    float m = -FLT_MAX;
#pragma unroll
    for (int i = 0; i < 4; i++) {
        vals[i] = __half22float2(p[tid + i * 256]);
        m = fmaxf(m, fmaxf(vals[i].x, vals[i].y));
    }
#pragma unroll
    for (int o = 16; o; o >>= 1) m = fmaxf(m, __shfl_xor_sync(0xffffffffu, m, o));
    if (l == 0) red[w] = m;
    __syncthreads();
    m = red[l & 7];
#pragma unroll
    for (int o = 4; o; o >>= 1) m = fmaxf(m, __shfl_xor_sync(0xffffffffu, m, o));

    float s = 0.f;
#pragma unroll
    for (int i = 0; i < 4; i++) {
        vals[i].x = __expf(vals[i].x - m);
        vals[i].y = __expf(vals[i].y - m);
        s += vals[i].x + vals[i].y;
    }
#pragma unroll
    for (int o = 16; o; o >>= 1) s += __shfl_xor_sync(0xffffffffu, s, o);
    __syncthreads();
    if (l == 0) red[w] = s;
    __syncthreads();
    s = red[l & 7];
#pragma unroll
    for (int o = 4; o; o >>= 1) s += __shfl_xor_sync(0xffffffffu, s, o);

    const float inv = 1.0f / s;
#pragma unroll
    for (int i = 0; i < 4; i++)
        p[tid + i * 256] = __floats2half2_rn(vals[i].x * inv, vals[i].y * inv);
}

// ---------------- host launcher ----------------
extern "C" void kernel_launch(void* const* d_in, const int* in_sizes, int n_in,
                              void* d_out, int out_size)
{
    const float* x      = (const float*)d_in[0];
    const float* w_qkv  = (const float*)d_in[1];
    const float* b_qkv  = (const float*)d_in[2];
    const float* q_g    = (const float*)d_in[3];
    const float* q_b    = (const float*)d_in[4];
    const float* k_g    = (const float*)d_in[5];
    const float* k_b    = (const float*)d_in[6];
    const float* w_proj = (const float*)d_in[7];
    const float* b_proj = (const float*)d_in[8];
    float* out = (float*)d_out;

    void *p_qkv, *p_qt, *p_kt, *p_vtT, *p_S, *p_ao;
    cudaGetSymbolAddress(&p_qkv, g_qkv);
    cudaGetSymbolAddress(&p_qt,  g_qt);
    cudaGetSymbolAddress(&p_kt,  g_kt);
    cudaGetSymbolAddress(&p_vtT, g_vtT);
    cudaGetSymbolAddress(&p_S,   g_S);
    cudaGetSymbolAddress(&p_ao,  g_ao);

    const int smem128 = 2 * (128 + 128) * 40 * 2;   // 40960 B
    const int smem96  = 2 * (128 + 96)  * 40 * 2;   // 35840 B
    cudaFuncSetAttribute((const void*)hgemm<128,128,false,false,false>, cudaFuncAttributeMaxDynamicSharedMemorySize, smem128);
    cudaFuncSetAttribute((const void*)hgemm<128,128,true, true, true >, cudaFuncAttributeMaxDynamicSharedMemorySize, smem128);
    cudaFuncSetAttribute((const void*)hgemm<96, 72, true, true, true >, cudaFuncAttributeMaxDynamicSharedMemorySize, smem96);
    cudaFuncSetAttribute((const void*)hgemm<128,128,true, false,false>, cudaFuncAttributeMaxDynamicSharedMemorySize, smem128);

    // 1) QKV: fp32 in, fp32 out
    hgemm<128,128,false,false,false><<<dim3(O3/128, MROWS/128, 1), 256, smem128>>>(
        x, w_qkv, b_qkv, (float*)p_qkv,
        DIM, DIM, DIM, O3, 0, 0, 0, 0, 1);

    // 2) LayerNorm + transpose -> fp16
    ln_split<<<(BATCH * SEQ * NHEAD) / 8, 256>>>(
        (const float*)p_qkv, q_g, q_b, k_g, k_b,
        (__half*)p_qt, (__half*)p_kt, (__half*)p_vtT);

    // 3) S = q @ k^T  (fp16 in, fp16 out), batched 32
    hgemm<128,128,true,true,true><<<dim3(SEQ/128, SEQ/128, BH), 256, smem128>>>(
        p_qt, p_kt, nullptr, p_S,
        HDIMP, HDIMP, HDIMP, SEQ,
        (long long)SEQ * HDIMP, (long long)SEQ * HDIMP,
        (long long)SEQ * SEQ, 0, 1);

    // 4) softmax (fp16 in/out)
    softmax_rows_h<<<BH * SEQ, 256>>>((__half2*)p_S);

    // 5) O = P @ V^T (fp16 in, fp16 out) -> ao[B,N,1152]
    hgemm<96,72,true,true,true><<<dim3(1, SEQ/128, BH), 256, smem96>>>(
        p_S, p_vtT, nullptr, p_ao,
        SEQ, SEQ, SEQ, DIM,
        (long long)SEQ * SEQ, (long long)HDIMP * SEQ,
        (long long)SEQ * DIM, (long long)HDIM, NHEAD);

    // 6) projection: fp16 A, fp32 B, fp32 out
    hgemm<128,128,true,false,false><<<dim3(DIM/128, MROWS/128, 1), 256, smem128>>>(
        p_ao, w_proj, b_proj, out,
        DIM, DIM, DIM, DIM, 0, 0, 0, 0, 1);
}

// round 5
// speedup vs baseline: 8.1453x; 1.6695x over previous
#include <cuda_runtime.h>
#include <cuda_fp16.h>
#include <cstdint>
#include <math.h>
#include <float.h>

#define BATCH 2
#define SEQ   2048
#define DIM   1152
#define NHEAD 16
#define HDIM  72
#define QKPAD 80               // head-dim padded to k-multiple of 16
#define O3    (3 * DIM)
#define MROWS (BATCH * SEQ)    // 4096
#define BH    (BATCH * NHEAD)  // 32
#define SCALE 0.1178511301977579f
#define LN_EPS 1e-5f

// ---------------- scratch ----------------
__device__ float  g_qkv[(size_t)MROWS * O3];            // fp32 [B,N,3,H,D]
__device__ __half g_x16[(size_t)MROWS * DIM];
__device__ __half g_wqkv16[(size_t)O3 * DIM];
__device__ __half g_wproj16[(size_t)DIM * DIM];
__device__ __half g_qt[(size_t)BH * SEQ * QKPAD];       // [bh][n][80], SCALE folded
__device__ __half g_kt[(size_t)BH * SEQ * QKPAD];
__device__ __half g_vtT[(size_t)BH * HDIM * SEQ];       // [bh][d][n]
__device__ __half g_ao[(size_t)MROWS * DIM];

__device__ __forceinline__ uint32_t packh2(float x, float y) {
    __half2 h = __floats2half2_rn(x, y);
    return *(uint32_t*)&h;
}
__device__ __forceinline__ void mma16(float c[4], const uint32_t a[4], const uint32_t b[2]) {
    asm volatile(
        "mma.sync.aligned.m16n8k16.row.col.f32.f16.f16.f32 "
        "{%0,%1,%2,%3}, {%4,%5,%6,%7}, {%8,%9}, {%0,%1,%2,%3};"
        : "+f"(c[0]), "+f"(c[1]), "+f"(c[2]), "+f"(c[3])
        : "r"(a[0]), "r"(a[1]), "r"(a[2]), "r"(a[3]), "r"(b[0]), "r"(b[1]));
}
__device__ __forceinline__ void cp16(uint32_t dst, const void* src) {
    asm volatile("cp.async.ca.shared.global [%0], [%1], 16;" :: "r"(dst), "l"(src));
}
#define CP_COMMIT() asm volatile("cp.async.commit_group;" ::: "memory")
#define CP_WAIT1()  asm volatile("cp.async.wait_group 1;" ::: "memory")

// ---------------- fp32 -> fp16 convert ----------------
__global__ void f2h(const float* __restrict__ src, __half* __restrict__ dst, int n4)
{
    int i = blockIdx.x * blockDim.x + threadIdx.x;
    if (i < n4) {
        float4 v = *(const float4*)(src + 4 * i);
        *(uint2*)(dst + 4 * i) = make_uint2(packh2(v.x, v.y), packh2(v.z, v.w));
    }
}

// ================= fp16 mma.sync GEMM (A16,B16 in; fp32 out + bias) =================
// C[m, n] = A[m,:K] @ B[n,:K]^T + bias. Block 128x128, K-chunk 32, 8 warps 2x4.
__global__ __launch_bounds__(256)
void hgemm(const __half* __restrict__ A, const __half* __restrict__ B,
           const float* __restrict__ bias, float* __restrict__ C,
           int K, int lda, int ldb, int ldc)
{
    extern __shared__ __half smh[];
    constexpr int PAD = 40;
    constexpr int ABUF = 128 * PAD;
    constexpr int BUF = 2 * ABUF;

    const int tid = threadIdx.x, wid = tid >> 5, lane = tid & 31;
    const int g = lane >> 2, t = lane & 3;
    const int wm = wid & 1, wn = wid >> 1;
    const int m0 = blockIdx.y * 128, n0 = blockIdx.x * 128;
    const int arow = tid >> 3, ac4 = (tid & 7) * 4;

    float acc[4][4][4];
#pragma unroll
    for (int mt = 0; mt < 4; mt++)
#pragma unroll
        for (int nt = 0; nt < 4; nt++)
#pragma unroll
            for (int j = 0; j < 4; j++) acc[mt][nt][j] = 0.f;

    const int nch = K / 32;
    {
        __half* As = smh; __half* Bs = smh + ABUF;
#pragma unroll
        for (int i = 0; i < 4; i++) {
            int r = arow + i * 32;
            *(uint2*)(As + r * PAD + ac4) = *(const uint2*)(A + (size_t)(m0 + r) * lda + ac4);
            *(uint2*)(Bs + r * PAD + ac4) = *(const uint2*)(B + (size_t)(n0 + r) * ldb + ac4);
        }
    }
    __syncthreads();

    for (int c = 0; c < nch; c++) {
        const int cur = c & 1;
        const bool pre = (c + 1 < nch);
        uint2 hav[4], hbv[4];
        if (pre) {
            const int k0 = (c + 1) * 32;
#pragma unroll
            for (int i = 0; i < 4; i++) {
                hav[i] = *(const uint2*)(A + (size_t)(m0 + arow + i * 32) * lda + k0 + ac4);
                hbv[i] = *(const uint2*)(B + (size_t)(n0 + arow + i * 32) * ldb + k0 + ac4);
            }
        }
        {
            const __half* As = smh + cur * BUF;
            const __half* Bs = As + ABUF;
#pragma unroll
            for (int ks = 0; ks < 2; ks++) {
                const int kk = ks * 16;
                uint32_t af[4][4], bf[4][2];
#pragma unroll
                for (int mt = 0; mt < 4; mt++) {
                    const __half* ap = As + (wm * 64 + mt * 16 + g) * PAD + kk + 2 * t;
                    af[mt][0] = *(const uint32_t*)ap;
                    af[mt][1] = *(const uint32_t*)(ap + 8 * PAD);
                    af[mt][2] = *(const uint32_t*)(ap + 8);
                    af[mt][3] = *(const uint32_t*)(ap + 8 * PAD + 8);
                }
#pragma unroll
                for (int nt = 0; nt < 4; nt++) {
                    const __half* bp = Bs + (wn * 32 + nt * 8 + g) * PAD + kk + 2 * t;
                    bf[nt][0] = *(const uint32_t*)bp;
                    bf[nt][1] = *(const uint32_t*)(bp + 8);
                }
#pragma unroll
                for (int mt = 0; mt < 4; mt++)
#pragma unroll
                    for (int nt = 0; nt < 4; nt++)
                        mma16(acc[mt][nt], af[mt], bf[nt]);
            }
        }
        if (pre) {
            __half* As = smh + (cur ^ 1) * BUF;
            __half* Bs = As + ABUF;
#pragma unroll
            for (int i = 0; i < 4; i++) {
                *(uint2*)(As + (arow + i * 32) * PAD + ac4) = hav[i];
                *(uint2*)(Bs + (arow + i * 32) * PAD + ac4) = hbv[i];
            }
        }
        __syncthreads();
    }

#pragma unroll
    for (int mt = 0; mt < 4; mt++) {
        const int r0 = m0 + wm * 64 + mt * 16 + g;
#pragma unroll
        for (int nt = 0; nt < 4; nt++) {
            const int col = n0 + wn * 32 + nt * 8 + 2 * t;
            const float bx = bias[col], by = bias[col + 1];
            *(float2*)(C + (size_t)r0 * ldc + col) =
                make_float2(acc[mt][nt][0] + bx, acc[mt][nt][1] + by);
            *(float2*)(C + (size_t)(r0 + 8) * ldc + col) =
                make_float2(acc[mt][nt][2] + bx, acc[mt][nt][3] + by);
        }
    }
}

// ------------- LayerNorm(q,k) + SCALE + transpose -> fp16 -------------
__global__ __launch_bounds__(256)
void ln_split(const float* __restrict__ qkv,
              const float* __restrict__ qg, const float* __restrict__ qb,
              const float* __restrict__ kg, const float* __restrict__ kb,
              __half* __restrict__ qt, __half* __restrict__ kt, __half* __restrict__ vtT)
{
    int task = blockIdx.x * 8 + (threadIdx.x >> 5);
    if (task >= BATCH * SEQ * NHEAD) return;
    const int lane = threadIdx.x & 31;
    const int h = task % NHEAD;
    const int n = (task / NHEAD) % SEQ;
    const int b = task / (NHEAD * SEQ);
    const int bh = b * NHEAD + h;

    const size_t ibase = ((size_t)(b * SEQ + n) * 3) * DIM + h * HDIM;
    const size_t oqk = ((size_t)bh * SEQ + n) * QKPAD;

    const float* q = qkv + ibase;
    const float* k = qkv + ibase + DIM;
    const float* v = qkv + ibase + 2 * DIM;

    {
        float x0 = q[lane], x1 = q[lane + 32];
        float x2 = (lane < 8) ? q[lane + 64] : 0.f;
        float s = x0 + x1 + x2;
#pragma unroll
        for (int o = 16; o; o >>= 1) s += __shfl_xor_sync(0xffffffffu, s, o);
        const float mu = s * (1.0f / HDIM);
        float d0 = x0 - mu, d1 = x1 - mu, d2 = (lane < 8) ? (x2 - mu) : 0.f;
        float vs = d0 * d0 + d1 * d1 + d2 * d2;
#pragma unroll
        for (int o = 16; o; o >>= 1) vs += __shfl_xor_sync(0xffffffffu, vs, o);
        const float inv = rsqrtf(vs * (1.0f / HDIM) + LN_EPS);
        qt[oqk + lane]      = __float2half_rn((d0 * inv * qg[lane]      + qb[lane])      * SCALE);
        qt[oqk + lane + 32] = __float2half_rn((d1 * inv * qg[lane + 32] + qb[lane + 32]) * SCALE);
        if (lane < 16)
            qt[oqk + lane + 64] = __float2half_rn((lane < 8) ?
                (d2 * inv * qg[lane + 64] + qb[lane + 64]) * SCALE : 0.f);
    }
    {
        float x0 = k[lane], x1 = k[lane + 32];
        float x2 = (lane < 8) ? k[lane + 64] : 0.f;
        float s = x0 + x1 + x2;
#pragma unroll
        for (int o = 16; o; o >>= 1) s += __shfl_xor_sync(0xffffffffu, s, o);
        const float mu = s * (1.0f / HDIM);
        float d0 = x0 - mu, d1 = x1 - mu, d2 = (lane < 8) ? (x2 - mu) : 0.f;
        float vs = d0 * d0 + d1 * d1 + d2 * d2;
#pragma unroll
        for (int o = 16; o; o >>= 1) vs += __shfl_xor_sync(0xffffffffu, vs, o);
        const float inv = rsqrtf(vs * (1.0f / HDIM) + LN_EPS);
        kt[oqk + lane]      = __float2half_rn(d0 * inv * kg[lane]      + kb[lane]);
        kt[oqk + lane + 32] = __float2half_rn(d1 * inv * kg[lane + 32] + kb[lane + 32]);
        if (lane < 16)
            kt[oqk + lane + 64] = __float2half_rn((lane < 8) ?
                (d2 * inv * kg[lane + 64] + kb[lane + 64]) : 0.f);
    }
    {
        __half* vb = vtT + (size_t)bh * HDIM * SEQ + n;
        vb[(size_t)lane * SEQ]        = __float2half_rn(v[lane]);
        vb[(size_t)(lane + 32) * SEQ] = __float2half_rn(v[lane + 32]);
        if (lane < 8) vb[(size_t)(lane + 64) * SEQ] = __float2half_rn(v[lane + 64]);
    }
}

// ================= fused flash attention =================
// Per block: 128 Q rows of one (b,h). Keys streamed in 64-wide tiles, cp.async x2.
// 8 warps x 16 rows. S tile in regs, online softmax fp32, P->A frags for PV.
#define TK 64
#define NTI (SEQ / TK)          // 32
#define QSTR 88                 // Q/K smem row stride (halves)
#define VSTR 72
#define SM_Q 0
#define SM_K (128 * QSTR)
#define SM_V (SM_K + 2 * TK * QSTR)
#define SM_FLASH ((SM_V + 2 * HDIM * VSTR) * 2)   // bytes

__global__ __launch_bounds__(256)
void flash_attn(const __half* __restrict__ qt, const __half* __restrict__ kt,
                const __half* __restrict__ vtT, __half* __restrict__ ao)
{
    extern __shared__ __half smh[];
    __half* Qs = smh + SM_Q;
    __half* Ks = smh + SM_K;
    __half* Vs = smh + SM_V;

    const int tid = threadIdx.x, wid = tid >> 5, lane = tid & 31;
    const int g = lane >> 2, t = lane & 3;
    const int m0 = blockIdx.x * 128;
    const int bh = blockIdx.y;

    const __half* Qg = qt + ((size_t)bh * SEQ + m0) * QKPAD;
    const __half* Kg = kt + (size_t)bh * SEQ * QKPAD;
    const __half* Vg = vtT + (size_t)bh * HDIM * SEQ;

    // Q: 128 rows x 80 halves = 1280 x 16B groups
    for (int idx = tid; idx < 1280; idx += 256) {
        int r = idx / 10, c8 = (idx % 10) * 8;
        *(uint4*)(Qs + r * QSTR + c8) = *(const uint4*)(Qg + (size_t)r * QKPAD + c8);
    }

    const uint32_t ks_a = (uint32_t)__cvta_generic_to_shared(Ks);
    const uint32_t vs_a = (uint32_t)__cvta_generic_to_shared(Vs);

    auto load_kv = [&](int ti) {
        const int buf = ti & 1;
        const int n0 = ti * TK;
        const uint32_t kd = ks_a + buf * (TK * QSTR * 2);
        for (int idx = tid; idx < 640; idx += 256) {     // 64 rows x 10 groups
            int r = idx / 10, c8 = (idx % 10) * 8;
            cp16(kd + (r * QSTR + c8) * 2, Kg + (size_t)(n0 + r) * QKPAD + c8);
        }
        const uint32_t vd = vs_a + buf * (HDIM * VSTR * 2);
        for (int idx = tid; idx < 576; idx += 256) {     // 72 rows x 8 groups
            int r = idx / 8, c8 = (idx % 8) * 8;
            cp16(vd + (r * VSTR + c8) * 2, Vg + (size_t)r * SEQ + n0 + c8);
        }
    };

    load_kv(0); CP_COMMIT();
    load_kv(1); CP_COMMIT();

    float m_lo = -1e30f, m_hi = -1e30f, l_lo = 0.f, l_hi = 0.f;
    float oacc[9][4];
#pragma unroll
    for (int nt = 0; nt < 9; nt++)
#pragma unroll
        for (int j = 0; j < 4; j++) oacc[nt][j] = 0.f;

    uint32_t qf[5][4];
    bool qloaded = false;

    for (int ti = 0; ti < NTI; ti++) {
        CP_WAIT1();
        __syncthreads();
        if (!qloaded) {
            qloaded = true;
#pragma unroll
            for (int s = 0; s < 5; s++) {
                const __half* qp = Qs + (wid * 16 + g) * QSTR + s * 16 + 2 * t;
                qf[s][0] = *(const uint32_t*)qp;
                qf[s][1] = *(const uint32_t*)(qp + 8 * QSTR);
                qf[s][2] = *(const uint32_t*)(qp + 8);
                qf[s][3] = *(const uint32_t*)(qp + 8 * QSTR + 8);
            }
        }
        const __half* Kb = Ks + (ti & 1) * TK * QSTR;
        const __half* Vb = Vs + (ti & 1) * HDIM * VSTR;

        // ---- S = Q @ K^T (16 rows x 64 keys per warp) ----
        float sacc[8][4];
#pragma unroll
        for (int nt = 0; nt < 8; nt++)
#pragma unroll
            for (int j = 0; j < 4; j++) sacc[nt][j] = 0.f;
#pragma unroll
        for (int s = 0; s < 5; s++) {
#pragma unroll
            for (int nt = 0; nt < 8; nt++) {
                const __half* bp = Kb + (nt * 8 + g) * QSTR + s * 16 + 2 * t;
                uint32_t bf[2] = { *(const uint32_t*)bp, *(const uint32_t*)(bp + 8) };
                mma16(sacc[nt], qf[s], bf);
            }
        }

        // ---- online softmax ----
        float mx_lo = -1e30f, mx_hi = -1e30f;
#pragma unroll
        for (int nt = 0; nt < 8; nt++) {
            mx_lo = fmaxf(mx_lo, fmaxf(sacc[nt][0], sacc[nt][1]));
            mx_hi = fmaxf(mx_hi, fmaxf(sacc[nt][2], sacc[nt][3]));
        }
        mx_lo = fmaxf(mx_lo, __shfl_xor_sync(0xffffffffu, mx_lo, 1));
        mx_lo = fmaxf(mx_lo, __shfl_xor_sync(0xffffffffu, mx_lo, 2));
        mx_hi = fmaxf(mx_hi, __shfl_xor_sync(0xffffffffu, mx_hi, 1));
        mx_hi = fmaxf(mx_hi, __shfl_xor_sync(0xffffffffu, mx_hi, 2));

        const float mn_lo = fmaxf(m_lo, mx_lo), mn_hi = fmaxf(m_hi, mx_hi);
        const float al_lo = __expf(m_lo - mn_lo), al_hi = __expf(m_hi - mn_hi);
        m_lo = mn_lo; m_hi = mn_hi;

        float s_lo = 0.f, s_hi = 0.f;
#pragma unroll
        for (int nt = 0; nt < 8; nt++) {
            sacc[nt][0] = __expf(sacc[nt][0] - mn_lo);
            sacc[nt][1] = __expf(sacc[nt][1] - mn_lo);
            sacc[nt][2] = __expf(sacc[nt][2] - mn_hi);
            sacc[nt][3] = __expf(sacc[nt][3] - mn_hi);
            s_lo += sacc[nt][0] + sacc[nt][1];
            s_hi += sacc[nt][2] + sacc[nt][3];
        }
        s_lo += __shfl_xor_sync(0xffffffffu, s_lo, 1);
        s_lo += __shfl_xor_sync(0xffffffffu, s_lo, 2);
        s_hi += __shfl_xor_sync(0xffffffffu, s_hi, 1);
        s_hi += __shfl_xor_sync(0xffffffffu, s_hi, 2);
        l_lo = l_lo * al_lo + s_lo;
        l_hi = l_hi * al_hi + s_hi;

#pragma unroll
        for (int nt = 0; nt < 9; nt++) {
            oacc[nt][0] *= al_lo; oacc[nt][1] *= al_lo;
            oacc[nt][2] *= al_hi; oacc[nt][3] *= al_hi;
        }

        // ---- O += P @ V ----
#pragma unroll
        for (int j = 0; j < 4; j++) {
            uint32_t a[4] = {
                packh2(sacc[2 * j][0],     sacc[2 * j][1]),
                packh2(sacc[2 * j][2],     sacc[2 * j][3]),
                packh2(sacc[2 * j + 1][0], sacc[2 * j + 1][1]),
                packh2(sacc[2 * j + 1][2], sacc[2 * j + 1][3]) };
#pragma unroll
            for (int nt = 0; nt < 9; nt++) {
                const __half* bp = Vb + (nt * 8 + g) * VSTR + j * 16 + 2 * t;
                uint32_t bf[2] = { *(const uint32_t*)bp, *(const uint32_t*)(bp + 8) };
                mma16(oacc[nt], a, bf);
            }
        }

        __syncthreads();
        if (ti + 2 < NTI) load_kv(ti + 2);
        CP_COMMIT();
    }

    // ---- epilogue ----
    const float inv_lo = 1.f / l_lo, inv_hi = 1.f / l_hi;
    const int b = bh >> 4, h = bh & 15;
    const int n_lo = m0 + wid * 16 + g;
    __half* po_lo = ao + ((size_t)(b * SEQ) + n_lo) * DIM + h * HDIM;
    __half* po_hi = po_lo + (size_t)8 * DIM;
#pragma unroll
    for (int nt = 0; nt < 9; nt++) {
        const int col = nt * 8 + 2 * t;
        *(__half2*)(po_lo + col) = __floats2half2_rn(oacc[nt][0] * inv_lo, oacc[nt][1] * inv_lo);
        *(__half2*)(po_hi + col) = __floats2half2_rn(oacc[nt][2] * inv_hi, oacc[nt][3] * inv_hi);
    }
}

// ---------------- host launcher ----------------
extern "C" void kernel_launch(void* const* d_in, const int* in_sizes, int n_in,
                              void* d_out, int out_size)
{
    const float* x      = (const float*)d_in[0];
    const float* w_qkv  = (const float*)d_in[1];
    const float* b_qkv  = (const float*)d_in[2];
    const float* q_g    = (const float*)d_in[3];
    const float* q_b    = (const float*)d_in[4];
    const float* k_g    = (const float*)d_in[5];
    const float* k_b    = (const float*)d_in[6];
    const float* w_proj = (const float*)d_in[7];
    const float* b_proj = (const float*)d_in[8];
    float* out = (float*)d_out;

    void *p_qkv, *p_x16, *p_wqkv16, *p_wproj16, *p_qt, *p_kt, *p_vtT, *p_ao;
    cudaGetSymbolAddress(&p_qkv,     g_qkv);
    cudaGetSymbolAddress(&p_x16,     g_x16);
    cudaGetSymbolAddress(&p_wqkv16,  g_wqkv16);
    cudaGetSymbolAddress(&p_wproj16, g_wproj16);
    cudaGetSymbolAddress(&p_qt,      g_qt);
    cudaGetSymbolAddress(&p_kt,      g_kt);
    cudaGetSymbolAddress(&p_vtT,     g_vtT);
    cudaGetSymbolAddress(&p_ao,      g_ao);

    const int smemG = 2 * 2 * 128 * 40 * 2;   // hgemm: 40960 B
    cudaFuncSetAttribute(hgemm, cudaFuncAttributeMaxDynamicSharedMemorySize, smemG);
    cudaFuncSetAttribute(flash_attn, cudaFuncAttributeMaxDynamicSharedMemorySize, SM_FLASH);

    // 0) fp32 -> fp16 operand conversion
    f2h<<<(MROWS * DIM / 4 + 255) / 256, 256>>>(x, (__half*)p_x16, MROWS * DIM / 4);
    f2h<<<((size_t)O3 * DIM / 4 + 255) / 256, 256>>>(w_qkv, (__half*)p_wqkv16, O3 * DIM / 4);
    f2h<<<(DIM * DIM / 4 + 255) / 256, 256>>>(w_proj, (__half*)p_wproj16, DIM * DIM / 4);

    // 1) QKV GEMM (fp16 in, fp32 out)
    hgemm<<<dim3(O3 / 128, MROWS / 128), 256, smemG>>>(
        (const __half*)p_x16, (const __half*)p_wqkv16, b_qkv, (float*)p_qkv,
        DIM, DIM, DIM, O3);

    // 2) LayerNorm + transpose -> fp16
    ln_split<<<(BATCH * SEQ * NHEAD) / 8, 256>>>(
        (const float*)p_qkv, q_g, q_b, k_g, k_b,
        (__half*)p_qt, (__half*)p_kt, (__half*)p_vtT);

    // 3) fused attention -> ao [B,N,1152] fp16
    flash_attn<<<dim3(SEQ / 128, BH), 256, SM_FLASH>>>(
        (const __half*)p_qt, (const __half*)p_kt, (const __half*)p_vtT, (__half*)p_ao);

    // 4) projection
    hgemm<<<dim3(DIM / 128, MROWS / 128), 256, smemG>>>(
        (const __half*)p_ao, (const __half*)p_wproj16, b_proj, out,
        DIM, DIM, DIM, DIM);
}

// round 6
// speedup vs baseline: 9.1245x; 1.1202x over previous
#include <cuda_runtime.h>
#include <cuda_fp16.h>
#include <cstdint>
#include <math.h>
#include <float.h>

#define BATCH 2
#define SEQ   2048
#define DIM   1152
#define NHEAD 16
#define HDIM  72
#define QKPAD 80
#define O3    (3 * DIM)
#define MROWS (BATCH * SEQ)    // 4096
#define BH    (BATCH * NHEAD)  // 32
#define SCALE 0.1178511301977579f
#define LN_EPS 1e-5f

// ---------------- scratch ----------------
__device__ float  g_qkv[(size_t)MROWS * O3];
__device__ __half g_x16[(size_t)MROWS * DIM];
__device__ __half g_wqkv16[(size_t)O3 * DIM];
__device__ __half g_wproj16[(size_t)DIM * DIM];
__device__ __half g_qt[(size_t)BH * SEQ * QKPAD];     // SCALE folded
__device__ __half g_kt[(size_t)BH * SEQ * QKPAD];
__device__ __half g_vt[(size_t)BH * SEQ * HDIM];      // natural [bh][n][72]
__device__ __half g_ao[(size_t)MROWS * DIM];

__device__ __forceinline__ uint32_t packh2(float x, float y) {
    __half2 h = __floats2half2_rn(x, y);
    return *(uint32_t*)&h;
}
__device__ __forceinline__ uint32_t s2u(const void* p) {
    return (uint32_t)__cvta_generic_to_shared(p);
}
__device__ __forceinline__ void mma16(float c[4], const uint32_t a[4], const uint32_t b[2]) {
    asm volatile(
        "mma.sync.aligned.m16n8k16.row.col.f32.f16.f16.f32 "
        "{%0,%1,%2,%3}, {%4,%5,%6,%7}, {%8,%9}, {%0,%1,%2,%3};"
        : "+f"(c[0]), "+f"(c[1]), "+f"(c[2]), "+f"(c[3])
        : "r"(a[0]), "r"(a[1]), "r"(a[2]), "r"(a[3]), "r"(b[0]), "r"(b[1]));
}
__device__ __forceinline__ void ldm4(uint32_t r[4], uint32_t a) {
    asm volatile("ldmatrix.sync.aligned.m8n8.x4.shared.b16 {%0,%1,%2,%3}, [%4];"
        : "=r"(r[0]), "=r"(r[1]), "=r"(r[2]), "=r"(r[3]) : "r"(a));
}
__device__ __forceinline__ void ldm4t(uint32_t r[4], uint32_t a) {
    asm volatile("ldmatrix.sync.aligned.m8n8.x4.trans.shared.b16 {%0,%1,%2,%3}, [%4];"
        : "=r"(r[0]), "=r"(r[1]), "=r"(r[2]), "=r"(r[3]) : "r"(a));
}
__device__ __forceinline__ void ldm2t(uint32_t r[2], uint32_t a) {
    asm volatile("ldmatrix.sync.aligned.m8n8.x2.trans.shared.b16 {%0,%1}, [%2];"
        : "=r"(r[0]), "=r"(r[1]) : "r"(a));
}
__device__ __forceinline__ void cp16(uint32_t dst, const void* src) {
    asm volatile("cp.async.ca.shared.global [%0], [%1], 16;" :: "r"(dst), "l"(src));
}
#define CP_COMMIT() asm volatile("cp.async.commit_group;" ::: "memory")
#define CP_WAIT1()  asm volatile("cp.async.wait_group 1;" ::: "memory")

// ---------------- fp32 -> fp16 convert ----------------
__global__ void f2h(const float* __restrict__ src, __half* __restrict__ dst, int n4)
{
    int i = blockIdx.x * blockDim.x + threadIdx.x;
    if (i < n4) {
        float4 v = *(const float4*)(src + 4 * i);
        *(uint2*)(dst + 4 * i) = make_uint2(packh2(v.x, v.y), packh2(v.z, v.w));
    }
}

// ================= fp16 GEMM v2: 256x128 block, 64x64 warp tile, ldmatrix ======
// C[m,n] = A[m,:K] @ B[n,:K]^T + bias (fp32 out). 8 warps = 4(M) x 2(N).
__global__ __launch_bounds__(256)
void hgemm(const __half* __restrict__ A, const __half* __restrict__ B,
           const float* __restrict__ bias, float* __restrict__ C,
           int K, int lda, int ldb, int ldc)
{
    extern __shared__ __half smh[];
    constexpr int PAD = 40;                 // halves/row (32 data + 8 pad), 80 B pitch
    constexpr int ABUF = 256 * PAD;
    constexpr int BBUF = 128 * PAD;

    const int tid = threadIdx.x, wid = tid >> 5, lane = tid & 31;
    const int g = lane >> 2, t = lane & 3;
    const int l8 = lane & 7, mi = lane >> 3;
    const int mrow = (mi & 1) * 8 + l8;     // row within 16-row frag
    const int mkof = (mi >> 1) * 8;         // k offset (halves)
    const int wm = wid >> 1, wn = wid & 1;
    const int m0 = blockIdx.y * 256, n0 = blockIdx.x * 128;
    const int ar = tid >> 2, ac = (tid & 3) * 8;   // cp.async row/col

    const uint32_t sb = s2u(smh);

    float acc[4][8][4];
#pragma unroll
    for (int mt = 0; mt < 4; mt++)
#pragma unroll
        for (int nt = 0; nt < 8; nt++)
#pragma unroll
            for (int j = 0; j < 4; j++) acc[mt][nt][j] = 0.f;

    auto load_chunk = [&](int c) {
        const int buf = c & 1, k0 = c * 32;
        const uint32_t da = sb + (buf * ABUF) * 2;
        const uint32_t db = sb + (2 * ABUF + buf * BBUF) * 2;
#pragma unroll
        for (int i = 0; i < 4; i++)
            cp16(da + ((ar + i * 64) * PAD + ac) * 2,
                 A + (size_t)(m0 + ar + i * 64) * lda + k0 + ac);
#pragma unroll
        for (int i = 0; i < 2; i++)
            cp16(db + ((ar + i * 64) * PAD + ac) * 2,
                 B + (size_t)(n0 + ar + i * 64) * ldb + k0 + ac);
    };

    const int nch = K / 32;
    load_chunk(0); CP_COMMIT();
    load_chunk(1); CP_COMMIT();

    for (int c = 0; c < nch; c++) {
        CP_WAIT1();
        __syncthreads();
        const int cur = c & 1;
        const uint32_t ab = sb + (cur * ABUF) * 2;
        const uint32_t bb = sb + (2 * ABUF + cur * BBUF) * 2;
#pragma unroll
        for (int ks = 0; ks < 2; ks++) {
            const int kk = ks * 16;
            uint32_t af[4][4], bf[4][4];
#pragma unroll
            for (int mt = 0; mt < 4; mt++)
                ldm4(af[mt], ab + ((wm * 64 + mt * 16 + mrow) * PAD + kk + mkof) * 2);
#pragma unroll
            for (int np = 0; np < 4; np++)
                ldm4(bf[np], bb + ((wn * 64 + np * 16 + mrow) * PAD + kk + mkof) * 2);
#pragma unroll
            for (int mt = 0; mt < 4; mt++)
#pragma unroll
                for (int np = 0; np < 4; np++) {
                    uint32_t b0[2] = { bf[np][0], bf[np][2] };
                    uint32_t b1[2] = { bf[np][1], bf[np][3] };
                    mma16(acc[mt][2 * np],     af[mt], b0);
                    mma16(acc[mt][2 * np + 1], af[mt], b1);
                }
        }
        __syncthreads();
        if (c + 2 < nch) load_chunk(c + 2);
        CP_COMMIT();
    }

#pragma unroll
    for (int mt = 0; mt < 4; mt++) {
        const int r0 = m0 + wm * 64 + mt * 16 + g;
#pragma unroll
        for (int nt = 0; nt < 8; nt++) {
            const int col = n0 + wn * 64 + nt * 8 + 2 * t;
            const float bx = bias[col], by = bias[col + 1];
            *(float2*)(C + (size_t)r0 * ldc + col) =
                make_float2(acc[mt][nt][0] + bx, acc[mt][nt][1] + by);
            *(float2*)(C + (size_t)(r0 + 8) * ldc + col) =
                make_float2(acc[mt][nt][2] + bx, acc[mt][nt][3] + by);
        }
    }
}

// ------------- LayerNorm(q,k) + SCALE + transpose -> fp16; V natural layout ----
__global__ __launch_bounds__(256)
void ln_split(const float* __restrict__ qkv,
              const float* __restrict__ qg, const float* __restrict__ qb,
              const float* __restrict__ kg, const float* __restrict__ kb,
              __half* __restrict__ qt, __half* __restrict__ kt, __half* __restrict__ vt)
{
    int task = blockIdx.x * 8 + (threadIdx.x >> 5);
    if (task >= BATCH * SEQ * NHEAD) return;
    const int lane = threadIdx.x & 31;
    const int h = task % NHEAD;
    const int n = (task / NHEAD) % SEQ;
    const int b = task / (NHEAD * SEQ);
    const int bh = b * NHEAD + h;

    const size_t ibase = ((size_t)(b * SEQ + n) * 3) * DIM + h * HDIM;
    const size_t oqk = ((size_t)bh * SEQ + n) * QKPAD;

    const float* q = qkv + ibase;
    const float* k = qkv + ibase + DIM;
    const float* v = qkv + ibase + 2 * DIM;

    {
        float x0 = q[lane], x1 = q[lane + 32];
        float x2 = (lane < 8) ? q[lane + 64] : 0.f;
        float s = x0 + x1 + x2;
#pragma unroll
        for (int o = 16; o; o >>= 1) s += __shfl_xor_sync(0xffffffffu, s, o);
        const float mu = s * (1.0f / HDIM);
        float d0 = x0 - mu, d1 = x1 - mu, d2 = (lane < 8) ? (x2 - mu) : 0.f;
        float vs = d0 * d0 + d1 * d1 + d2 * d2;
#pragma unroll
        for (int o = 16; o; o >>= 1) vs += __shfl_xor_sync(0xffffffffu, vs, o);
        const float inv = rsqrtf(vs * (1.0f / HDIM) + LN_EPS);
        qt[oqk + lane]      = __float2half_rn((d0 * inv * qg[lane]      + qb[lane])      * SCALE);
        qt[oqk + lane + 32] = __float2half_rn((d1 * inv * qg[lane + 32] + qb[lane + 32]) * SCALE);
        if (lane < 16)
            qt[oqk + lane + 64] = __float2half_rn((lane < 8) ?
                (d2 * inv * qg[lane + 64] + qb[lane + 64]) * SCALE : 0.f);
    }
    {
        float x0 = k[lane], x1 = k[lane + 32];
        float x2 = (lane < 8) ? k[lane + 64] : 0.f;
        float s = x0 + x1 + x2;
#pragma unroll
        for (int o = 16; o; o >>= 1) s += __shfl_xor_sync(0xffffffffu, s, o);
        const float mu = s * (1.0f / HDIM);
        float d0 = x0 - mu, d1 = x1 - mu, d2 = (lane < 8) ? (x2 - mu) : 0.f;
        float vs = d0 * d0 + d1 * d1 + d2 * d2;
#pragma unroll
        for (int o = 16; o; o >>= 1) vs += __shfl_xor_sync(0xffffffffu, vs, o);
        const float inv = rsqrtf(vs * (1.0f / HDIM) + LN_EPS);
        kt[oqk + lane]      = __float2half_rn(d0 * inv * kg[lane]      + kb[lane]);
        kt[oqk + lane + 32] = __float2half_rn(d1 * inv * kg[lane + 32] + kb[lane + 32]);
        if (lane < 16)
            kt[oqk + lane + 64] = __float2half_rn((lane < 8) ?
                (d2 * inv * kg[lane + 64] + kb[lane + 64]) : 0.f);
    }
    {
        __half* vb = vt + ((size_t)bh * SEQ + n) * HDIM;
        vb[lane]      = __float2half_rn(v[lane]);
        vb[lane + 32] = __float2half_rn(v[lane + 32]);
        if (lane < 8) vb[lane + 64] = __float2half_rn(v[lane + 64]);
    }
}

// ================= fused flash attention v2 (ldmatrix) =================
#define TK 64
#define NTI (SEQ / TK)          // 32
#define QSTR 88                 // 176 B pitch (odd x16B: conflict-free)
#define VSTR 72                 // 144 B pitch (odd x16B)
#define SMH_Q 0
#define SMH_K (128 * QSTR)
#define SMH_V (SMH_K + 2 * TK * QSTR)
#define SM_FLASH ((SMH_V + 2 * TK * VSTR) * 2)   // bytes = 63488

__global__ __launch_bounds__(256)
void flash_attn(const __half* __restrict__ qt, const __half* __restrict__ kt,
                const __half* __restrict__ vt, __half* __restrict__ ao)
{
    extern __shared__ __half smh[];
    const int tid = threadIdx.x, wid = tid >> 5, lane = tid & 31;
    const int g = lane >> 2, t = lane & 3;
    const int l8 = lane & 7, mi = lane >> 3;
    const int mrow = (mi & 1) * 8 + l8;
    const int mkof = (mi >> 1) * 8;
    const int m0 = blockIdx.x * 128;
    const int bh = blockIdx.y;

    const __half* Qg = qt + ((size_t)bh * SEQ + m0) * QKPAD;
    const __half* Kg = kt + (size_t)bh * SEQ * QKPAD;
    const __half* Vg = vt + (size_t)bh * SEQ * HDIM;

    const uint32_t sb = s2u(smh);

    // Q: 128 rows x 10 chunks
    for (int idx = tid; idx < 1280; idx += 256) {
        int r = idx / 10, c8 = (idx % 10) * 8;
        *(uint4*)(smh + SMH_Q + r * QSTR + c8) = *(const uint4*)(Qg + (size_t)r * QKPAD + c8);
    }

    auto load_kv = [&](int ti) {
        const int buf = ti & 1;
        const int n0 = ti * TK;
        const uint32_t kd = sb + (SMH_K + buf * TK * QSTR) * 2;
        for (int idx = tid; idx < 640; idx += 256) {
            int r = idx / 10, c8 = (idx % 10) * 8;
            cp16(kd + (r * QSTR + c8) * 2, Kg + (size_t)(n0 + r) * QKPAD + c8);
        }
        const uint32_t vd = sb + (SMH_V + buf * TK * VSTR) * 2;
        for (int idx = tid; idx < 576; idx += 256) {
            int r = idx / 9, c8 = (idx % 9) * 8;
            cp16(vd + (r * VSTR + c8) * 2, Vg + (size_t)(n0 + r) * HDIM + c8);
        }
    };

    load_kv(0); CP_COMMIT();
    load_kv(1); CP_COMMIT();

    float m_lo = -1e30f, m_hi = -1e30f, l_lo = 0.f, l_hi = 0.f;
    float oacc[9][4];
#pragma unroll
    for (int nt = 0; nt < 9; nt++)
#pragma unroll
        for (int j = 0; j < 4; j++) oacc[nt][j] = 0.f;

    uint32_t qf[5][4];
    bool qloaded = false;

    for (int ti = 0; ti < NTI; ti++) {
        CP_WAIT1();
        __syncthreads();
        if (!qloaded) {
            qloaded = true;
#pragma unroll
            for (int s = 0; s < 5; s++)
                ldm4(qf[s], sb + (SMH_Q + (wid * 16 + mrow) * QSTR + s * 16 + mkof) * 2);
        }
        const uint32_t kbase = sb + (SMH_K + (ti & 1) * TK * QSTR) * 2;
        const uint32_t vbase = sb + (SMH_V + (ti & 1) * TK * VSTR) * 2;

        // ---- S = Q @ K^T ----
        float sacc[8][4];
#pragma unroll
        for (int nt = 0; nt < 8; nt++)
#pragma unroll
            for (int j = 0; j < 4; j++) sacc[nt][j] = 0.f;
#pragma unroll
        for (int s = 0; s < 5; s++) {
#pragma unroll
            for (int np = 0; np < 4; np++) {
                uint32_t kf[4];
                ldm4(kf, kbase + ((np * 16 + mrow) * QSTR + s * 16 + mkof) * 2);
                uint32_t b0[2] = { kf[0], kf[2] }, b1[2] = { kf[1], kf[3] };
                mma16(sacc[2 * np],     qf[s], b0);
                mma16(sacc[2 * np + 1], qf[s], b1);
            }
        }

        // ---- online softmax ----
        float mx_lo = -1e30f, mx_hi = -1e30f;
#pragma unroll
        for (int nt = 0; nt < 8; nt++) {
            mx_lo = fmaxf(mx_lo, fmaxf(sacc[nt][0], sacc[nt][1]));
            mx_hi = fmaxf(mx_hi, fmaxf(sacc[nt][2], sacc[nt][3]));
        }
        mx_lo = fmaxf(mx_lo, __shfl_xor_sync(0xffffffffu, mx_lo, 1));
        mx_lo = fmaxf(mx_lo, __shfl_xor_sync(0xffffffffu, mx_lo, 2));
        mx_hi = fmaxf(mx_hi, __shfl_xor_sync(0xffffffffu, mx_hi, 1));
        mx_hi = fmaxf(mx_hi, __shfl_xor_sync(0xffffffffu, mx_hi, 2));

        const float mn_lo = fmaxf(m_lo, mx_lo), mn_hi = fmaxf(m_hi, mx_hi);
        const float al_lo = __expf(m_lo - mn_lo), al_hi = __expf(m_hi - mn_hi);
        m_lo = mn_lo; m_hi = mn_hi;

        float s_lo = 0.f, s_hi = 0.f;
#pragma unroll
        for (int nt = 0; nt < 8; nt++) {
            sacc[nt][0] = __expf(sacc[nt][0] - mn_lo);
            sacc[nt][1] = __expf(sacc[nt][1] - mn_lo);
            sacc[nt][2] = __expf(sacc[nt][2] - mn_hi);
            sacc[nt][3] = __expf(sacc[nt][3] - mn_hi);
            s_lo += sacc[nt][0] + sacc[nt][1];
            s_hi += sacc[nt][2] + sacc[nt][3];
        }
        s_lo += __shfl_xor_sync(0xffffffffu, s_lo, 1);
        s_lo += __shfl_xor_sync(0xffffffffu, s_lo, 2);
        s_hi += __shfl_xor_sync(0xffffffffu, s_hi, 1);
        s_hi += __shfl_xor_sync(0xffffffffu, s_hi, 2);
        l_lo = l_lo * al_lo + s_lo;
        l_hi = l_hi * al_hi + s_hi;

#pragma unroll
        for (int nt = 0; nt < 9; nt++) {
            oacc[nt][0] *= al_lo; oacc[nt][1] *= al_lo;
            oacc[nt][2] *= al_hi; oacc[nt][3] *= al_hi;
        }

        // ---- O += P @ V ----
#pragma unroll
        for (int j = 0; j < 4; j++) {
            uint32_t a[4] = {
                packh2(sacc[2 * j][0],     sacc[2 * j][1]),
                packh2(sacc[2 * j][2],     sacc[2 * j][3]),
                packh2(sacc[2 * j + 1][0], sacc[2 * j + 1][1]),
                packh2(sacc[2 * j + 1][2], sacc[2 * j + 1][3]) };
            const uint32_t vrow = vbase + ((j * 16 + mrow) * VSTR) * 2;
#pragma unroll
            for (int np = 0; np < 4; np++) {
                uint32_t vf[4];
                ldm4t(vf, vrow + np * 32 + (mi >> 1) * 16);
                uint32_t b0[2] = { vf[0], vf[1] }, b1[2] = { vf[2], vf[3] };
                mma16(oacc[2 * np],     a, b0);
                mma16(oacc[2 * np + 1], a, b1);
            }
            {
                uint32_t v2[2];
                ldm2t(v2, vrow + 128);
                mma16(oacc[8], a, v2);
            }
        }

        __syncthreads();
        if (ti + 2 < NTI) load_kv(ti + 2);
        CP_COMMIT();
    }

    // ---- epilogue ----
    const float inv_lo = 1.f / l_lo, inv_hi = 1.f / l_hi;
    const int b = bh >> 4, h = bh & 15;
    const int n_lo = m0 + wid * 16 + g;
    __half* po_lo = ao + ((size_t)(b * SEQ) + n_lo) * DIM + h * HDIM;
    __half* po_hi = po_lo + (size_t)8 * DIM;
#pragma unroll
    for (int nt = 0; nt < 9; nt++) {
        const int col = nt * 8 + 2 * t;
        *(__half2*)(po_lo + col) = __floats2half2_rn(oacc[nt][0] * inv_lo, oacc[nt][1] * inv_lo);
        *(__half2*)(po_hi + col) = __floats2half2_rn(oacc[nt][2] * inv_hi, oacc[nt][3] * inv_hi);
    }
}

// ---------------- host launcher ----------------
extern "C" void kernel_launch(void* const* d_in, const int* in_sizes, int n_in,
                              void* d_out, int out_size)
{
    const float* x      = (const float*)d_in[0];
    const float* w_qkv  = (const float*)d_in[1];
    const float* b_qkv  = (const float*)d_in[2];
    const float* q_g    = (const float*)d_in[3];
    const float* q_b    = (const float*)d_in[4];
    const float* k_g    = (const float*)d_in[5];
    const float* k_b    = (const float*)d_in[6];
    const float* w_proj = (const float*)d_in[7];
    const float* b_proj = (const float*)d_in[8];
    float* out = (float*)d_out;

    void *p_qkv, *p_x16, *p_wqkv16, *p_wproj16, *p_qt, *p_kt, *p_vt, *p_ao;
    cudaGetSymbolAddress(&p_qkv,     g_qkv);
    cudaGetSymbolAddress(&p_x16,     g_x16);
    cudaGetSymbolAddress(&p_wqkv16,  g_wqkv16);
    cudaGetSymbolAddress(&p_wproj16, g_wproj16);
    cudaGetSymbolAddress(&p_qt,      g_qt);
    cudaGetSymbolAddress(&p_kt,      g_kt);
    cudaGetSymbolAddress(&p_vt,      g_vt);
    cudaGetSymbolAddress(&p_ao,      g_ao);

    const int smemG = (2 * 256 * 40 + 2 * 128 * 40) * 2;   // 61440 B
    cudaFuncSetAttribute(hgemm, cudaFuncAttributeMaxDynamicSharedMemorySize, smemG);
    cudaFuncSetAttribute(flash_attn, cudaFuncAttributeMaxDynamicSharedMemorySize, SM_FLASH);

    // 0) fp32 -> fp16 operand conversion
    f2h<<<(MROWS * DIM / 4 + 255) / 256, 256>>>(x, (__half*)p_x16, MROWS * DIM / 4);
    f2h<<<((size_t)O3 * DIM / 4 + 255) / 256, 256>>>(w_qkv, (__half*)p_wqkv16, O3 * DIM / 4);
    f2h<<<(DIM * DIM / 4 + 255) / 256, 256>>>(w_proj, (__half*)p_wproj16, DIM * DIM / 4);

    // 1) QKV GEMM
    hgemm<<<dim3(O3 / 128, MROWS / 256), 256, smemG>>>(
        (const __half*)p_x16, (const __half*)p_wqkv16, b_qkv, (float*)p_qkv,
        DIM, DIM, DIM, O3);

    // 2) LayerNorm + transpose -> fp16
    ln_split<<<(BATCH * SEQ * NHEAD) / 8, 256>>>(
        (const float*)p_qkv, q_g, q_b, k_g, k_b,
        (__half*)p_qt, (__half*)p_kt, (__half*)p_vt);

    // 3) fused attention
    flash_attn<<<dim3(SEQ / 128, BH), 256, SM_FLASH>>>(
        (const __half*)p_qt, (const __half*)p_kt, (const __half*)p_vt, (__half*)p_ao);

    // 4) projection
    hgemm<<<dim3(DIM / 128, MROWS / 256), 256, smemG>>>(
        (const __half*)p_ao, (const __half*)p_wproj16, b_proj, out,
        DIM, DIM, DIM, DIM);
}

// round 7
// speedup vs baseline: 9.3162x; 1.0210x over previous
#include <cuda_runtime.h>
#include <cuda_fp16.h>
#include <cstdint>
#include <math.h>
#include <float.h>

#define BATCH 2
#define SEQ   2048
#define DIM   1152
#define NHEAD 16
#define HDIM  72
#define QKPAD 80
#define O3    (3 * DIM)
#define MROWS (BATCH * SEQ)    // 4096
#define BH    (BATCH * NHEAD)  // 32
#define SCALE 0.1178511301977579f
#define LN_EPS 1e-5f

// ---------------- scratch ----------------
__device__ float  g_qkv[(size_t)MROWS * O3];
__device__ __half g_x16[(size_t)MROWS * DIM];
__device__ __half g_wqkv16[(size_t)O3 * DIM];
__device__ __half g_wproj16[(size_t)DIM * DIM];
__device__ __half g_qt[(size_t)BH * SEQ * QKPAD];     // SCALE folded
__device__ __half g_kt[(size_t)BH * SEQ * QKPAD];
__device__ __half g_vt[(size_t)BH * SEQ * HDIM];      // natural [bh][n][72]
__device__ __half g_ao[(size_t)MROWS * DIM];

__device__ __forceinline__ uint32_t packh2(float x, float y) {
    __half2 h = __floats2half2_rn(x, y);
    return *(uint32_t*)&h;
}
__device__ __forceinline__ uint32_t s2u(const void* p) {
    return (uint32_t)__cvta_generic_to_shared(p);
}
__device__ __forceinline__ void mma16(float c[4], const uint32_t a[4], const uint32_t b[2]) {
    asm volatile(
        "mma.sync.aligned.m16n8k16.row.col.f32.f16.f16.f32 "
        "{%0,%1,%2,%3}, {%4,%5,%6,%7}, {%8,%9}, {%0,%1,%2,%3};"
        : "+f"(c[0]), "+f"(c[1]), "+f"(c[2]), "+f"(c[3])
        : "r"(a[0]), "r"(a[1]), "r"(a[2]), "r"(a[3]), "r"(b[0]), "r"(b[1]));
}
__device__ __forceinline__ void ldm4(uint32_t r[4], uint32_t a) {
    asm volatile("ldmatrix.sync.aligned.m8n8.x4.shared.b16 {%0,%1,%2,%3}, [%4];"
        : "=r"(r[0]), "=r"(r[1]), "=r"(r[2]), "=r"(r[3]) : "r"(a));
}
__device__ __forceinline__ void ldm4t(uint32_t r[4], uint32_t a) {
    asm volatile("ldmatrix.sync.aligned.m8n8.x4.trans.shared.b16 {%0,%1,%2,%3}, [%4];"
        : "=r"(r[0]), "=r"(r[1]), "=r"(r[2]), "=r"(r[3]) : "r"(a));
}
__device__ __forceinline__ void ldm2t(uint32_t r[2], uint32_t a) {
    asm volatile("ldmatrix.sync.aligned.m8n8.x2.trans.shared.b16 {%0,%1}, [%2];"
        : "=r"(r[0]), "=r"(r[1]) : "r"(a));
}
__device__ __forceinline__ void cp16(uint32_t dst, const void* src) {
    asm volatile("cp.async.ca.shared.global [%0], [%1], 16;" :: "r"(dst), "l"(src));
}
#define CP_COMMIT() asm volatile("cp.async.commit_group;" ::: "memory")
#define CP_WAIT1()  asm volatile("cp.async.wait_group 1;" ::: "memory")
#define CP_WAIT2()  asm volatile("cp.async.wait_group 2;" ::: "memory")

// ---------------- fused fp32 -> fp16 convert (3 tensors, 1 launch) -------------
__global__ void f2h3(const float* __restrict__ s0, __half* __restrict__ d0, int n0,
                     const float* __restrict__ s1, __half* __restrict__ d1, int n1,
                     const float* __restrict__ s2, __half* __restrict__ d2, int n2)
{
    int i = blockIdx.x * blockDim.x + threadIdx.x;
    const float* s; __half* d; int j;
    if (i < n0)           { s = s0; d = d0; j = i; }
    else if (i < n0 + n1) { s = s1; d = d1; j = i - n0; }
    else if (i < n0 + n1 + n2) { s = s2; d = d2; j = i - n0 - n1; }
    else return;
    float4 v = ((const float4*)s)[j];
    ((uint2*)d)[j] = make_uint2(packh2(v.x, v.y), packh2(v.z, v.w));
}

// ================= fp16 GEMM v3: 256x128 block, 4-stage pipeline ======
// C[m,n] = A[m,:K] @ B[n,:K]^T + bias (fp32 out). 8 warps = 4(M) x 2(N), 64x64 warp tile.
__global__ __launch_bounds__(256)
void hgemm(const __half* __restrict__ A, const __half* __restrict__ B,
           const float* __restrict__ bias, float* __restrict__ C,
           int K, int lda, int ldb, int ldc)
{
    extern __shared__ __half smh[];
    constexpr int PAD = 40;                  // halves/row, 80 B pitch
    constexpr int STG = (256 + 128) * PAD;   // halves per stage
    constexpr int BOF = 256 * PAD;           // B offset within stage

    const int tid = threadIdx.x, wid = tid >> 5, lane = tid & 31;
    const int g = lane >> 2, t = lane & 3;
    const int l8 = lane & 7, mi = lane >> 3;
    const int mrow = (mi & 1) * 8 + l8;
    const int mkof = (mi >> 1) * 8;
    const int wm = wid >> 1, wn = wid & 1;
    const int m0 = blockIdx.y * 256, n0 = blockIdx.x * 128;
    const int ar = tid >> 2, ac = (tid & 3) * 8;

    const uint32_t sb = s2u(smh);

    float acc[4][8][4];
#pragma unroll
    for (int mt = 0; mt < 4; mt++)
#pragma unroll
        for (int nt = 0; nt < 8; nt++)
#pragma unroll
            for (int j = 0; j < 4; j++) acc[mt][nt][j] = 0.f;

    auto load_chunk = [&](int c) {
        const int k0 = c * 32;
        const uint32_t da = sb + ((c & 3) * STG) * 2;
        const uint32_t db = da + BOF * 2;
#pragma unroll
        for (int i = 0; i < 4; i++)
            cp16(da + ((ar + i * 64) * PAD + ac) * 2,
                 A + (size_t)(m0 + ar + i * 64) * lda + k0 + ac);
#pragma unroll
        for (int i = 0; i < 2; i++)
            cp16(db + ((ar + i * 64) * PAD + ac) * 2,
                 B + (size_t)(n0 + ar + i * 64) * ldb + k0 + ac);
    };

    const int nch = K / 32;
    load_chunk(0); CP_COMMIT();
    load_chunk(1); CP_COMMIT();
    load_chunk(2); CP_COMMIT();

    for (int c = 0; c < nch; c++) {
        CP_WAIT2();
        __syncthreads();
        if (c + 3 < nch) load_chunk(c + 3);
        CP_COMMIT();                         // unconditional: keeps group counting sound

        const uint32_t ab = sb + ((c & 3) * STG) * 2;
        const uint32_t bb = ab + BOF * 2;
#pragma unroll
        for (int ks = 0; ks < 2; ks++) {
            const int kk = ks * 16;
            uint32_t af[4][4], bf[4][4];
#pragma unroll
            for (int mt = 0; mt < 4; mt++)
                ldm4(af[mt], ab + ((wm * 64 + mt * 16 + mrow) * PAD + kk + mkof) * 2);
#pragma unroll
            for (int np = 0; np < 4; np++)
                ldm4(bf[np], bb + ((wn * 64 + np * 16 + mrow) * PAD + kk + mkof) * 2);
#pragma unroll
            for (int mt = 0; mt < 4; mt++)
#pragma unroll
                for (int np = 0; np < 4; np++) {
                    uint32_t b0[2] = { bf[np][0], bf[np][2] };
                    uint32_t b1[2] = { bf[np][1], bf[np][3] };
                    mma16(acc[mt][2 * np],     af[mt], b0);
                    mma16(acc[mt][2 * np + 1], af[mt], b1);
                }
        }
    }

#pragma unroll
    for (int mt = 0; mt < 4; mt++) {
        const int r0 = m0 + wm * 64 + mt * 16 + g;
#pragma unroll
        for (int nt = 0; nt < 8; nt++) {
            const int col = n0 + wn * 64 + nt * 8 + 2 * t;
            const float bx = bias[col], by = bias[col + 1];
            *(float2*)(C + (size_t)r0 * ldc + col) =
                make_float2(acc[mt][nt][0] + bx, acc[mt][nt][1] + by);
            *(float2*)(C + (size_t)(r0 + 8) * ldc + col) =
                make_float2(acc[mt][nt][2] + bx, acc[mt][nt][3] + by);
        }
    }
}

// ------------- LayerNorm(q,k) + SCALE + transpose -> fp16; V natural layout ----
__global__ __launch_bounds__(256)
void ln_split(const float* __restrict__ qkv,
              const float* __restrict__ qg, const float* __restrict__ qb,
              const float* __restrict__ kg, const float* __restrict__ kb,
              __half* __restrict__ qt, __half* __restrict__ kt, __half* __restrict__ vt)
{
    int task = blockIdx.x * 8 + (threadIdx.x >> 5);
    if (task >= BATCH * SEQ * NHEAD) return;
    const int lane = threadIdx.x & 31;
    const int h = task % NHEAD;
    const int n = (task / NHEAD) % SEQ;
    const int b = task / (NHEAD * SEQ);
    const int bh = b * NHEAD + h;

    const size_t ibase = ((size_t)(b * SEQ + n) * 3) * DIM + h * HDIM;
    const size_t oqk = ((size_t)bh * SEQ + n) * QKPAD;

    const float* q = qkv + ibase;
    const float* k = qkv + ibase + DIM;
    const float* v = qkv + ibase + 2 * DIM;

    {
        float x0 = q[lane], x1 = q[lane + 32];
        float x2 = (lane < 8) ? q[lane + 64] : 0.f;
        float s = x0 + x1 + x2;
#pragma unroll
        for (int o = 16; o; o >>= 1) s += __shfl_xor_sync(0xffffffffu, s, o);
        const float mu = s * (1.0f / HDIM);
        float d0 = x0 - mu, d1 = x1 - mu, d2 = (lane < 8) ? (x2 - mu) : 0.f;
        float vs = d0 * d0 + d1 * d1 + d2 * d2;
#pragma unroll
        for (int o = 16; o; o >>= 1) vs += __shfl_xor_sync(0xffffffffu, vs, o);
        const float inv = rsqrtf(vs * (1.0f / HDIM) + LN_EPS);
        qt[oqk + lane]      = __float2half_rn((d0 * inv * qg[lane]      + qb[lane])      * SCALE);
        qt[oqk + lane + 32] = __float2half_rn((d1 * inv * qg[lane + 32] + qb[lane + 32]) * SCALE);
        if (lane < 16)
            qt[oqk + lane + 64] = __float2half_rn((lane < 8) ?
                (d2 * inv * qg[lane + 64] + qb[lane + 64]) * SCALE : 0.f);
    }
    {
        float x0 = k[lane], x1 = k[lane + 32];
        float x2 = (lane < 8) ? k[lane + 64] : 0.f;
        float s = x0 + x1 + x2;
#pragma unroll
        for (int o = 16; o; o >>= 1) s += __shfl_xor_sync(0xffffffffu, s, o);
        const float mu = s * (1.0f / HDIM);
        float d0 = x0 - mu, d1 = x1 - mu, d2 = (lane < 8) ? (x2 - mu) : 0.f;
        float vs = d0 * d0 + d1 * d1 + d2 * d2;
#pragma unroll
        for (int o = 16; o; o >>= 1) vs += __shfl_xor_sync(0xffffffffu, vs, o);
        const float inv = rsqrtf(vs * (1.0f / HDIM) + LN_EPS);
        kt[oqk + lane]      = __float2half_rn(d0 * inv * kg[lane]      + kb[lane]);
        kt[oqk + lane + 32] = __float2half_rn(d1 * inv * kg[lane + 32] + kb[lane + 32]);
        if (lane < 16)
            kt[oqk + lane + 64] = __float2half_rn((lane < 8) ?
                (d2 * inv * kg[lane + 64] + kb[lane + 64]) : 0.f);
    }
    {
        __half* vb = vt + ((size_t)bh * SEQ + n) * HDIM;
        vb[lane]      = __float2half_rn(v[lane]);
        vb[lane + 32] = __float2half_rn(v[lane + 32]);
        if (lane < 8) vb[lane + 64] = __float2half_rn(v[lane + 64]);
    }
}

// ================= fused flash attention v3 (3-stage pipeline) =================
#define TK 64
#define NTI (SEQ / TK)          // 32
#define QSTR 88                 // 176 B pitch (conflict-free for ldmatrix)
#define VSTR 72                 // 144 B pitch
#define SMH_Q 0
#define SMH_K (128 * QSTR)                    // 11264
#define SMH_V (SMH_K + 3 * TK * QSTR)         // 28160
#define SM_FLASH ((SMH_V + 3 * TK * VSTR) * 2)   // 83968 bytes

__global__ __launch_bounds__(256)
void flash_attn(const __half* __restrict__ qt, const __half* __restrict__ kt,
                const __half* __restrict__ vt, __half* __restrict__ ao)
{
    extern __shared__ __half smh[];
    const int tid = threadIdx.x, wid = tid >> 5, lane = tid & 31;
    const int g = lane >> 2, t = lane & 3;
    const int l8 = lane & 7, mi = lane >> 3;
    const int mrow = (mi & 1) * 8 + l8;
    const int mkof = (mi >> 1) * 8;
    const int m0 = blockIdx.x * 128;
    const int bh = blockIdx.y;

    const __half* Qg = qt + ((size_t)bh * SEQ + m0) * QKPAD;
    const __half* Kg = kt + (size_t)bh * SEQ * QKPAD;
    const __half* Vg = vt + (size_t)bh * SEQ * HDIM;

    const uint32_t sb = s2u(smh);

    // Q: 128 rows x 10 chunks (plain stores; visible after first __syncthreads)
    for (int idx = tid; idx < 1280; idx += 256) {
        int r = idx / 10, c8 = (idx % 10) * 8;
        *(uint4*)(smh + SMH_Q + r * QSTR + c8) = *(const uint4*)(Qg + (size_t)r * QKPAD + c8);
    }

    auto load_kv = [&](int ti) {
        const int buf = ti % 3;
        const int n0 = ti * TK;
        const uint32_t kd = sb + (SMH_K + buf * TK * QSTR) * 2;
        for (int idx = tid; idx < 640; idx += 256) {
            int r = idx / 10, c8 = (idx % 10) * 8;
            cp16(kd + (r * QSTR + c8) * 2, Kg + (size_t)(n0 + r) * QKPAD + c8);
        }
        const uint32_t vd = sb + (SMH_V + buf * TK * VSTR) * 2;
        for (int idx = tid; idx < 576; idx += 256) {
            int r = idx / 9, c8 = (idx % 9) * 8;
            cp16(vd + (r * VSTR + c8) * 2, Vg + (size_t)(n0 + r) * HDIM + c8);
        }
    };

    load_kv(0); CP_COMMIT();
    load_kv(1); CP_COMMIT();

    float m_lo = -1e30f, m_hi = -1e30f, l_lo = 0.f, l_hi = 0.f;
    float oacc[9][4];
#pragma unroll
    for (int nt = 0; nt < 9; nt++)
#pragma unroll
        for (int j = 0; j < 4; j++) oacc[nt][j] = 0.f;

    uint32_t qf[5][4];
    bool qloaded = false;

    for (int ti = 0; ti < NTI; ti++) {
        CP_WAIT1();
        __syncthreads();
        if (ti + 2 < NTI) load_kv(ti + 2);
        CP_COMMIT();

        if (!qloaded) {
            qloaded = true;
#pragma unroll
            for (int s = 0; s < 5; s++)
                ldm4(qf[s], sb + (SMH_Q + (wid * 16 + mrow) * QSTR + s * 16 + mkof) * 2);
        }
        const uint32_t kbase = sb + (SMH_K + (ti % 3) * TK * QSTR) * 2;
        const uint32_t vbase = sb + (SMH_V + (ti % 3) * TK * VSTR) * 2;

        // ---- S = Q @ K^T ----
        float sacc[8][4];
#pragma unroll
        for (int nt = 0; nt < 8; nt++)
#pragma unroll
            for (int j = 0; j < 4; j++) sacc[nt][j] = 0.f;
#pragma unroll
        for (int s = 0; s < 5; s++) {
#pragma unroll
            for (int np = 0; np < 4; np++) {
                uint32_t kf[4];
                ldm4(kf, kbase + ((np * 16 + mrow) * QSTR + s * 16 + mkof) * 2);
                uint32_t b0[2] = { kf[0], kf[2] }, b1[2] = { kf[1], kf[3] };
                mma16(sacc[2 * np],     qf[s], b0);
                mma16(sacc[2 * np + 1], qf[s], b1);
            }
        }

        // ---- online softmax ----
        float mx_lo = -1e30f, mx_hi = -1e30f;
#pragma unroll
        for (int nt = 0; nt < 8; nt++) {
            mx_lo = fmaxf(mx_lo, fmaxf(sacc[nt][0], sacc[nt][1]));
            mx_hi = fmaxf(mx_hi, fmaxf(sacc[nt][2], sacc[nt][3]));
        }
        mx_lo = fmaxf(mx_lo, __shfl_xor_sync(0xffffffffu, mx_lo, 1));
        mx_lo = fmaxf(mx_lo, __shfl_xor_sync(0xffffffffu, mx_lo, 2));
        mx_hi = fmaxf(mx_hi, __shfl_xor_sync(0xffffffffu, mx_hi, 1));
        mx_hi = fmaxf(mx_hi, __shfl_xor_sync(0xffffffffu, mx_hi, 2));

        const float mn_lo = fmaxf(m_lo, mx_lo), mn_hi = fmaxf(m_hi, mx_hi);
        const float al_lo = __expf(m_lo - mn_lo), al_hi = __expf(m_hi - mn_hi);
        m_lo = mn_lo; m_hi = mn_hi;

        float s_lo = 0.f, s_hi = 0.f;
#pragma unroll
        for (int nt = 0; nt < 8; nt++) {
            sacc[nt][0] = __expf(sacc[nt][0] - mn_lo);
            sacc[nt][1] = __expf(sacc[nt][1] - mn_lo);
            sacc[nt][2] = __expf(sacc[nt][2] - mn_hi);
            sacc[nt][3] = __expf(sacc[nt][3] - mn_hi);
            s_lo += sacc[nt][0] + sacc[nt][1];
            s_hi += sacc[nt][2] + sacc[nt][3];
        }
        s_lo += __shfl_xor_sync(0xffffffffu, s_lo, 1);
        s_lo += __shfl_xor_sync(0xffffffffu, s_lo, 2);
        s_hi += __shfl_xor_sync(0xffffffffu, s_hi, 1);
        s_hi += __shfl_xor_sync(0xffffffffu, s_hi, 2);
        l_lo = l_lo * al_lo + s_lo;
        l_hi = l_hi * al_hi + s_hi;

#pragma unroll
        for (int nt = 0; nt < 9; nt++) {
            oacc[nt][0] *= al_lo; oacc[nt][1] *= al_lo;
            oacc[nt][2] *= al_hi; oacc[nt][3] *= al_hi;
        }

        // ---- O += P @ V ----
#pragma unroll
        for (int j = 0; j < 4; j++) {
            uint32_t a[4] = {
                packh2(sacc[2 * j][0],     sacc[2 * j][1]),
                packh2(sacc[2 * j][2],     sacc[2 * j][3]),
                packh2(sacc[2 * j + 1][0], sacc[2 * j + 1][1]),
                packh2(sacc[2 * j + 1][2], sacc[2 * j + 1][3]) };
            const uint32_t vrow = vbase + ((j * 16 + mrow) * VSTR) * 2;
#pragma unroll
            for (int np = 0; np < 4; np++) {
                uint32_t vf[4];
                ldm4t(vf, vrow + np * 32 + (mi >> 1) * 16);
                uint32_t b0[2] = { vf[0], vf[1] }, b1[2] = { vf[2], vf[3] };
                mma16(oacc[2 * np],     a, b0);
                mma16(oacc[2 * np + 1], a, b1);
            }
            {
                uint32_t v2[2];
                ldm2t(v2, vrow + 128);
                mma16(oacc[8], a, v2);
            }
        }
    }

    // ---- epilogue ----
    const float inv_lo = 1.f / l_lo, inv_hi = 1.f / l_hi;
    const int b = bh >> 4, h = bh & 15;
    const int n_lo = m0 + wid * 16 + g;
    __half* po_lo = ao + ((size_t)(b * SEQ) + n_lo) * DIM + h * HDIM;
    __half* po_hi = po_lo + (size_t)8 * DIM;
#pragma unroll
    for (int nt = 0; nt < 9; nt++) {
        const int col = nt * 8 + 2 * t;
        *(__half2*)(po_lo + col) = __floats2half2_rn(oacc[nt][0] * inv_lo, oacc[nt][1] * inv_lo);
        *(__half2*)(po_hi + col) = __floats2half2_rn(oacc[nt][2] * inv_hi, oacc[nt][3] * inv_hi);
    }
}

// ---------------- host launcher ----------------
extern "C" void kernel_launch(void* const* d_in, const int* in_sizes, int n_in,
                              void* d_out, int out_size)
{
    const float* x      = (const float*)d_in[0];
    const float* w_qkv  = (const float*)d_in[1];
    const float* b_qkv  = (const float*)d_in[2];
    const float* q_g    = (const float*)d_in[3];
    const float* q_b    = (const float*)d_in[4];
    const float* k_g    = (const float*)d_in[5];
    const float* k_b    = (const float*)d_in[6];
    const float* w_proj = (const float*)d_in[7];
    const float* b_proj = (const float*)d_in[8];
    float* out = (float*)d_out;

    void *p_qkv, *p_x16, *p_wqkv16, *p_wproj16, *p_qt, *p_kt, *p_vt, *p_ao;
    cudaGetSymbolAddress(&p_qkv,     g_qkv);
    cudaGetSymbolAddress(&p_x16,     g_x16);
    cudaGetSymbolAddress(&p_wqkv16,  g_wqkv16);
    cudaGetSymbolAddress(&p_wproj16, g_wproj16);
    cudaGetSymbolAddress(&p_qt,      g_qt);
    cudaGetSymbolAddress(&p_kt,      g_kt);
    cudaGetSymbolAddress(&p_vt,      g_vt);
    cudaGetSymbolAddress(&p_ao,      g_ao);

    const int smemG = 4 * (256 + 128) * 40 * 2;   // 122880 B
    cudaFuncSetAttribute(hgemm, cudaFuncAttributeMaxDynamicSharedMemorySize, smemG);
    cudaFuncSetAttribute(flash_attn, cudaFuncAttributeMaxDynamicSharedMemorySize, SM_FLASH);

    // 0) fp32 -> fp16 conversion, single launch
    const int n0 = MROWS * DIM / 4, n1 = O3 * DIM / 4, n2 = DIM * DIM / 4;
    f2h3<<<(n0 + n1 + n2 + 255) / 256, 256>>>(
        x, (__half*)p_x16, n0,
        w_qkv, (__half*)p_wqkv16, n1,
        w_proj, (__half*)p_wproj16, n2);

    // 1) QKV GEMM
    hgemm<<<dim3(O3 / 128, MROWS / 256), 256, smemG>>>(
        (const __half*)p_x16, (const __half*)p_wqkv16, b_qkv, (float*)p_qkv,
        DIM, DIM, DIM, O3);

    // 2) LayerNorm + transpose -> fp16
    ln_split<<<(BATCH * SEQ * NHEAD) / 8, 256>>>(
        (const float*)p_qkv, q_g, q_b, k_g, k_b,
        (__half*)p_qt, (__half*)p_kt, (__half*)p_vt);

    // 3) fused attention
    flash_attn<<<dim3(SEQ / 128, BH), 256, SM_FLASH>>>(
        (const __half*)p_qt, (const __half*)p_kt, (const __half*)p_vt, (__half*)p_ao);

    // 4) projection
    hgemm<<<dim3(DIM / 128, MROWS / 256), 256, smemG>>>(
        (const __half*)p_ao, (const __half*)p_wproj16, b_proj, out,
        DIM, DIM, DIM, DIM);
}

// round 8
// speedup vs baseline: 9.6510x; 1.0359x over previous
#include <cuda_runtime.h>
#include <cuda_fp16.h>
#include <cstdint>
#include <math.h>
#include <float.h>

#define BATCH 2
#define SEQ   2048
#define DIM   1152
#define NHEAD 16
#define HDIM  72
#define QKPAD 80
#define O3    (3 * DIM)
#define MROWS (BATCH * SEQ)    // 4096
#define BH    (BATCH * NHEAD)  // 32
#define SCALE 0.1178511301977579f
#define QSC   (0.1178511301977579f * 1.4426950408889634f)   // SCALE * log2(e)
#define LN_EPS 1e-5f

// ---------------- scratch ----------------
__device__ float  g_qkv[(size_t)MROWS * O3];
__device__ __half g_x16[(size_t)MROWS * DIM];
__device__ __half g_wqkv16[(size_t)O3 * DIM];
__device__ __half g_wproj16[(size_t)DIM * DIM];
__device__ __half g_qt[(size_t)BH * SEQ * QKPAD];     // QSC folded
__device__ __half g_kt[(size_t)BH * SEQ * QKPAD];
__device__ __half g_vt[(size_t)BH * SEQ * HDIM];      // natural [bh][n][72]
__device__ __half g_ao[(size_t)MROWS * DIM];

__device__ __forceinline__ uint32_t packh2(float x, float y) {
    __half2 h = __floats2half2_rn(x, y);
    return *(uint32_t*)&h;
}
__device__ __forceinline__ uint32_t s2u(const void* p) {
    return (uint32_t)__cvta_generic_to_shared(p);
}
__device__ __forceinline__ float ex2f(float x) {
    float r; asm("ex2.approx.f32 %0, %1;" : "=f"(r) : "f"(x)); return r;
}
__device__ __forceinline__ void mma16(float c[4], const uint32_t a[4], const uint32_t b[2]) {
    asm volatile(
        "mma.sync.aligned.m16n8k16.row.col.f32.f16.f16.f32 "
        "{%0,%1,%2,%3}, {%4,%5,%6,%7}, {%8,%9}, {%0,%1,%2,%3};"
        : "+f"(c[0]), "+f"(c[1]), "+f"(c[2]), "+f"(c[3])
        : "r"(a[0]), "r"(a[1]), "r"(a[2]), "r"(a[3]), "r"(b[0]), "r"(b[1]));
}
__device__ __forceinline__ void ldm4(uint32_t r[4], uint32_t a) {
    asm volatile("ldmatrix.sync.aligned.m8n8.x4.shared.b16 {%0,%1,%2,%3}, [%4];"
        : "=r"(r[0]), "=r"(r[1]), "=r"(r[2]), "=r"(r[3]) : "r"(a));
}
__device__ __forceinline__ void ldm4t(uint32_t r[4], uint32_t a) {
    asm volatile("ldmatrix.sync.aligned.m8n8.x4.trans.shared.b16 {%0,%1,%2,%3}, [%4];"
        : "=r"(r[0]), "=r"(r[1]), "=r"(r[2]), "=r"(r[3]) : "r"(a));
}
__device__ __forceinline__ void ldm2t(uint32_t r[2], uint32_t a) {
    asm volatile("ldmatrix.sync.aligned.m8n8.x2.trans.shared.b16 {%0,%1}, [%2];"
        : "=r"(r[0]), "=r"(r[1]) : "r"(a));
}
__device__ __forceinline__ void cp16(uint32_t dst, const void* src) {
    asm volatile("cp.async.ca.shared.global [%0], [%1], 16;" :: "r"(dst), "l"(src));
}
#define CP_COMMIT() asm volatile("cp.async.commit_group;" ::: "memory")
#define CP_WAIT1()  asm volatile("cp.async.wait_group 1;" ::: "memory")
#define CP_WAIT2()  asm volatile("cp.async.wait_group 2;" ::: "memory")

// ---------------- fused fp32 -> fp16 convert ----------------
__global__ void f2h3(const float* __restrict__ s0, __half* __restrict__ d0, int n0,
                     const float* __restrict__ s1, __half* __restrict__ d1, int n1,
                     const float* __restrict__ s2, __half* __restrict__ d2, int n2)
{
    int i = blockIdx.x * blockDim.x + threadIdx.x;
    const float* s; __half* d; int j;
    if (i < n0)                { s = s0; d = d0; j = i; }
    else if (i < n0 + n1)      { s = s1; d = d1; j = i - n0; }
    else if (i < n0 + n1 + n2) { s = s2; d = d2; j = i - n0 - n1; }
    else return;
    float4 v = ((const float4*)s)[j];
    ((uint2*)d)[j] = make_uint2(packh2(v.x, v.y), packh2(v.z, v.w));
}

// ================= fp16 GEMM v4: 128x128 block, 128 thr, 4-stage, 2 CTA/SM ======
__global__ __launch_bounds__(128)
void hgemm(const __half* __restrict__ A, const __half* __restrict__ B,
           const float* __restrict__ bias, float* __restrict__ C,
           int K, int lda, int ldb, int ldc)
{
    extern __shared__ __half smh[];
    constexpr int PAD = 40;              // 80 B pitch
    constexpr int STG = 256 * PAD;       // 128 A rows + 128 B rows per stage
    constexpr int BOF = 128 * PAD;

    const int tid = threadIdx.x, wid = tid >> 5, lane = tid & 31;
    const int g = lane >> 2, t = lane & 3;
    const int l8 = lane & 7, mi = lane >> 3;
    const int mrow = (mi & 1) * 8 + l8;
    const int mkof = (mi >> 1) * 8;
    const int wm = wid >> 1, wn = wid & 1;
    const int m0 = blockIdx.y * 128, n0 = blockIdx.x * 128;
    const int ar = tid >> 2, ac = (tid & 3) * 8;    // 32 rows per pass

    const uint32_t sb = s2u(smh);

    float acc[4][8][4];
#pragma unroll
    for (int mt = 0; mt < 4; mt++)
#pragma unroll
        for (int nt = 0; nt < 8; nt++)
#pragma unroll
            for (int j = 0; j < 4; j++) acc[mt][nt][j] = 0.f;

    auto load_chunk = [&](int c) {
        const int k0 = c * 32;
        const uint32_t da = sb + ((c & 3) * STG) * 2;
        const uint32_t db = da + BOF * 2;
#pragma unroll
        for (int i = 0; i < 4; i++) {
            cp16(da + ((ar + i * 32) * PAD + ac) * 2,
                 A + (size_t)(m0 + ar + i * 32) * lda + k0 + ac);
            cp16(db + ((ar + i * 32) * PAD + ac) * 2,
                 B + (size_t)(n0 + ar + i * 32) * ldb + k0 + ac);
        }
    };

    const int nch = K / 32;
    load_chunk(0); CP_COMMIT();
    load_chunk(1); CP_COMMIT();
    load_chunk(2); CP_COMMIT();

    for (int c = 0; c < nch; c++) {
        CP_WAIT2();
        __syncthreads();
        if (c + 3 < nch) load_chunk(c + 3);
        CP_COMMIT();

        const uint32_t ab = sb + ((c & 3) * STG) * 2;
        const uint32_t bb = ab + BOF * 2;
#pragma unroll
        for (int ks = 0; ks < 2; ks++) {
            const int kk = ks * 16;
            uint32_t af[4][4], bf[4][4];
#pragma unroll
            for (int mt = 0; mt < 4; mt++)
                ldm4(af[mt], ab + ((wm * 64 + mt * 16 + mrow) * PAD + kk + mkof) * 2);
#pragma unroll
            for (int np = 0; np < 4; np++)
                ldm4(bf[np], bb + ((wn * 64 + np * 16 + mrow) * PAD + kk + mkof) * 2);
#pragma unroll
            for (int mt = 0; mt < 4; mt++)
#pragma unroll
                for (int np = 0; np < 4; np++) {
                    uint32_t b0[2] = { bf[np][0], bf[np][2] };
                    uint32_t b1[2] = { bf[np][1], bf[np][3] };
                    mma16(acc[mt][2 * np],     af[mt], b0);
                    mma16(acc[mt][2 * np + 1], af[mt], b1);
                }
        }
    }

#pragma unroll
    for (int mt = 0; mt < 4; mt++) {
        const int r0 = m0 + wm * 64 + mt * 16 + g;
#pragma unroll
        for (int nt = 0; nt < 8; nt++) {
            const int col = n0 + wn * 64 + nt * 8 + 2 * t;
            const float bx = bias[col], by = bias[col + 1];
            *(float2*)(C + (size_t)r0 * ldc + col) =
                make_float2(acc[mt][nt][0] + bx, acc[mt][nt][1] + by);
            *(float2*)(C + (size_t)(r0 + 8) * ldc + col) =
                make_float2(acc[mt][nt][2] + bx, acc[mt][nt][3] + by);
        }
    }
}

// ------------- LayerNorm(q,k) + QSC + transpose -> fp16; V natural layout ----
__global__ __launch_bounds__(256)
void ln_split(const float* __restrict__ qkv,
              const float* __restrict__ qg, const float* __restrict__ qb,
              const float* __restrict__ kg, const float* __restrict__ kb,
              __half* __restrict__ qt, __half* __restrict__ kt, __half* __restrict__ vt)
{
    int task = blockIdx.x * 8 + (threadIdx.x >> 5);
    if (task >= BATCH * SEQ * NHEAD) return;
    const int lane = threadIdx.x & 31;
    const int h = task % NHEAD;
    const int n = (task / NHEAD) % SEQ;
    const int b = task / (NHEAD * SEQ);
    const int bh = b * NHEAD + h;

    const size_t ibase = ((size_t)(b * SEQ + n) * 3) * DIM + h * HDIM;
    const size_t oqk = ((size_t)bh * SEQ + n) * QKPAD;

    const float* q = qkv + ibase;
    const float* k = qkv + ibase + DIM;
    const float* v = qkv + ibase + 2 * DIM;

    {
        float x0 = q[lane], x1 = q[lane + 32];
        float x2 = (lane < 8) ? q[lane + 64] : 0.f;
        float s = x0 + x1 + x2;
#pragma unroll
        for (int o = 16; o; o >>= 1) s += __shfl_xor_sync(0xffffffffu, s, o);
        const float mu = s * (1.0f / HDIM);
        float d0 = x0 - mu, d1 = x1 - mu, d2 = (lane < 8) ? (x2 - mu) : 0.f;
        float vs = d0 * d0 + d1 * d1 + d2 * d2;
#pragma unroll
        for (int o = 16; o; o >>= 1) vs += __shfl_xor_sync(0xffffffffu, vs, o);
        const float inv = rsqrtf(vs * (1.0f / HDIM) + LN_EPS);
        qt[oqk + lane]      = __float2half_rn((d0 * inv * qg[lane]      + qb[lane])      * QSC);
        qt[oqk + lane + 32] = __float2half_rn((d1 * inv * qg[lane + 32] + qb[lane + 32]) * QSC);
        if (lane < 16)
            qt[oqk + lane + 64] = __float2half_rn((lane < 8) ?
                (d2 * inv * qg[lane + 64] + qb[lane + 64]) * QSC : 0.f);
    }
    {
        float x0 = k[lane], x1 = k[lane + 32];
        float x2 = (lane < 8) ? k[lane + 64] : 0.f;
        float s = x0 + x1 + x2;
#pragma unroll
        for (int o = 16; o; o >>= 1) s += __shfl_xor_sync(0xffffffffu, s, o);
        const float mu = s * (1.0f / HDIM);
        float d0 = x0 - mu, d1 = x1 - mu, d2 = (lane < 8) ? (x2 - mu) : 0.f;
        float vs = d0 * d0 + d1 * d1 + d2 * d2;
#pragma unroll
        for (int o = 16; o; o >>= 1) vs += __shfl_xor_sync(0xffffffffu, vs, o);
        const float inv = rsqrtf(vs * (1.0f / HDIM) + LN_EPS);
        kt[oqk + lane]      = __float2half_rn(d0 * inv * kg[lane]      + kb[lane]);
        kt[oqk + lane + 32] = __float2half_rn(d1 * inv * kg[lane + 32] + kb[lane + 32]);
        if (lane < 16)
            kt[oqk + lane + 64] = __float2half_rn((lane < 8) ?
                (d2 * inv * kg[lane + 64] + kb[lane + 64]) : 0.f);
    }
    {
        __half* vb = vt + ((size_t)bh * SEQ + n) * HDIM;
        vb[lane]      = __float2half_rn(v[lane]);
        vb[lane + 32] = __float2half_rn(v[lane + 32]);
        if (lane < 8) vb[lane + 64] = __float2half_rn(v[lane + 64]);
    }
}

// ================= fused flash attention v4 =================
// ones-column row-sum, log2-domain softmax, ballot-skip rescale, 2 CTA/SM.
#define TK 64
#define NTI (SEQ / TK)          // 32
#define QSTR 88                 // 176 B pitch
#define VSTR 88                 // 176 B pitch; col 72 = 1.0, 73..79 = 0
#define SMH_Q 0
#define SMH_K (128 * QSTR)                        // 11264
#define SMH_V (SMH_K + 3 * TK * QSTR)             // 28160
#define SM_FLASH ((SMH_V + 3 * TK * VSTR) * 2)    // 90112 B

__global__ __launch_bounds__(256, 2)
void flash_attn(const __half* __restrict__ qt, const __half* __restrict__ kt,
                const __half* __restrict__ vt, __half* __restrict__ ao)
{
    extern __shared__ __half smh[];
    const int tid = threadIdx.x, wid = tid >> 5, lane = tid & 31;
    const int g = lane >> 2, t = lane & 3;
    const int l8 = lane & 7, mi = lane >> 3;
    const int mrow = (mi & 1) * 8 + l8;
    const int mkof = (mi >> 1) * 8;
    const int m0 = blockIdx.x * 128;
    const int bh = blockIdx.y;

    const __half* Qg = qt + ((size_t)bh * SEQ + m0) * QKPAD;
    const __half* Kg = kt + (size_t)bh * SEQ * QKPAD;
    const __half* Vg = vt + (size_t)bh * SEQ * HDIM;

    const uint32_t sb = s2u(smh);

    // Q staging + ones-column init (plain stores; visible after first sync)
    for (int idx = tid; idx < 1280; idx += 256) {
        int r = idx / 10, c8 = (idx % 10) * 8;
        *(uint4*)(smh + SMH_Q + r * QSTR + c8) = *(const uint4*)(Qg + (size_t)r * QKPAD + c8);
    }
    if (tid < 3 * TK) {   // V cols 72..79: {1,0,0,0,0,0,0,0}, once per buffer
        uint4 ones = make_uint4(0x00003C00u, 0u, 0u, 0u);
        *(uint4*)(smh + SMH_V + tid * VSTR + 72) = ones;
    }

    auto load_kv = [&](int ti, int buf) {
        const int n0 = ti * TK;
        const uint32_t kd = sb + (SMH_K + buf * TK * QSTR) * 2;
#pragma unroll
        for (int i = 0; i < 3; i++) {
            int idx = tid + i * 256;
            if (idx < 640) {
                int r = idx / 10, c8 = (idx % 10) * 8;
                cp16(kd + (r * QSTR + c8) * 2, Kg + (size_t)(n0 + r) * QKPAD + c8);
            }
        }
        const uint32_t vd = sb + (SMH_V + buf * TK * VSTR) * 2;
#pragma unroll
        for (int i = 0; i < 3; i++) {
            int idx = tid + i * 256;
            if (idx < 576) {
                int r = idx / 9, c8 = (idx % 9) * 8;
                cp16(vd + (r * VSTR + c8) * 2, Vg + (size_t)(n0 + r) * HDIM + c8);
            }
        }
    };

    load_kv(0, 0); CP_COMMIT();
    load_kv(1, 1); CP_COMMIT();

    float m_lo = -1e30f, m_hi = -1e30f;
    float oacc[10][4];
#pragma unroll
    for (int nt = 0; nt < 10; nt++)
#pragma unroll
        for (int j = 0; j < 4; j++) oacc[nt][j] = 0.f;

    uint32_t qf[5][4];
    bool qloaded = false;
    int bufL = 2, bufC = 0;

    for (int ti = 0; ti < NTI; ti++) {
        CP_WAIT1();
        __syncthreads();
        if (ti + 2 < NTI) load_kv(ti + 2, bufL);
        CP_COMMIT();
        bufL = (bufL == 2) ? 0 : bufL + 1;

        if (!qloaded) {
            qloaded = true;
#pragma unroll
            for (int s = 0; s < 5; s++)
                ldm4(qf[s], sb + (SMH_Q + (wid * 16 + mrow) * QSTR + s * 16 + mkof) * 2);
        }
        const uint32_t kbase = sb + (SMH_K + bufC * TK * QSTR) * 2;
        const uint32_t vbase = sb + (SMH_V + bufC * TK * VSTR) * 2;
        bufC = (bufC == 2) ? 0 : bufC + 1;

        // ---- S = Q @ K^T (log2 domain) ----
        float sacc[8][4];
#pragma unroll
        for (int nt = 0; nt < 8; nt++)
#pragma unroll
            for (int j = 0; j < 4; j++) sacc[nt][j] = 0.f;
#pragma unroll
        for (int s = 0; s < 5; s++) {
#pragma unroll
            for (int np = 0; np < 4; np++) {
                uint32_t kf[4];
                ldm4(kf, kbase + ((np * 16 + mrow) * QSTR + s * 16 + mkof) * 2);
                uint32_t b0[2] = { kf[0], kf[2] }, b1[2] = { kf[1], kf[3] };
                mma16(sacc[2 * np],     qf[s], b0);
                mma16(sacc[2 * np + 1], qf[s], b1);
            }
        }

        // ---- online softmax (2^x) ----
        float mx_lo = -1e30f, mx_hi = -1e30f;
#pragma unroll
        for (int nt = 0; nt < 8; nt++) {
            mx_lo = fmaxf(mx_lo, fmaxf(sacc[nt][0], sacc[nt][1]));
            mx_hi = fmaxf(mx_hi, fmaxf(sacc[nt][2], sacc[nt][3]));
        }
        mx_lo = fmaxf(mx_lo, __shfl_xor_sync(0xffffffffu, mx_lo, 1));
        mx_lo = fmaxf(mx_lo, __shfl_xor_sync(0xffffffffu, mx_lo, 2));
        mx_hi = fmaxf(mx_hi, __shfl_xor_sync(0xffffffffu, mx_hi, 1));
        mx_hi = fmaxf(mx_hi, __shfl_xor_sync(0xffffffffu, mx_hi, 2));

        const float mn_lo = fmaxf(m_lo, mx_lo), mn_hi = fmaxf(m_hi, mx_hi);
        const float al_lo = ex2f(m_lo - mn_lo), al_hi = ex2f(m_hi - mn_hi);
        m_lo = mn_lo; m_hi = mn_hi;

#pragma unroll
        for (int nt = 0; nt < 8; nt++) {
            sacc[nt][0] = ex2f(sacc[nt][0] - mn_lo);
            sacc[nt][1] = ex2f(sacc[nt][1] - mn_lo);
            sacc[nt][2] = ex2f(sacc[nt][2] - mn_hi);
            sacc[nt][3] = ex2f(sacc[nt][3] - mn_hi);
        }

        if (__ballot_sync(0xffffffffu, (al_lo != 1.f) || (al_hi != 1.f))) {
#pragma unroll
            for (int nt = 0; nt < 10; nt++) {
                oacc[nt][0] *= al_lo; oacc[nt][1] *= al_lo;
                oacc[nt][2] *= al_hi; oacc[nt][3] *= al_hi;
            }
        }

        // ---- O += P @ V  (col 72 of V = 1.0 -> row sum of P in oacc[9][0/2]) ----
#pragma unroll
        for (int j = 0; j < 4; j++) {
            uint32_t a[4] = {
                packh2(sacc[2 * j][0],     sacc[2 * j][1]),
                packh2(sacc[2 * j][2],     sacc[2 * j][3]),
                packh2(sacc[2 * j + 1][0], sacc[2 * j + 1][1]),
                packh2(sacc[2 * j + 1][2], sacc[2 * j + 1][3]) };
            const uint32_t vrow = vbase + ((j * 16 + mrow) * VSTR) * 2;
#pragma unroll
            for (int np = 0; np < 4; np++) {
                uint32_t vf[4];
                ldm4t(vf, vrow + np * 32 + (mi >> 1) * 16);
                uint32_t b0[2] = { vf[0], vf[1] }, b1[2] = { vf[2], vf[3] };
                mma16(oacc[2 * np],     a, b0);
                mma16(oacc[2 * np + 1], a, b1);
            }
            {
                uint32_t v2[2];
                ldm2t(v2, vrow + 128);       // cols 64..71
                mma16(oacc[8], a, v2);
            }
            {
                uint32_t v2[2];
                ldm2t(v2, vrow + 144);       // cols 72..79 (ones column)
                mma16(oacc[9], a, v2);
            }
        }
    }

    // ---- epilogue: l from ones column, broadcast within group-of-4 ----
    const float l_lo = __shfl_sync(0xffffffffu, oacc[9][0], lane & 28);
    const float l_hi = __shfl_sync(0xffffffffu, oacc[9][2], lane & 28);
    const float inv_lo = 1.f / l_lo, inv_hi = 1.f / l_hi;
    const int b = bh >> 4, h = bh & 15;
    const int n_lo = m0 + wid * 16 + g;
    __half* po_lo = ao + ((size_t)(b * SEQ) + n_lo) * DIM + h * HDIM;
    __half* po_hi = po_lo + (size_t)8 * DIM;
#pragma unroll
    for (int nt = 0; nt < 9; nt++) {
        const int col = nt * 8 + 2 * t;
        *(__half2*)(po_lo + col) = __floats2half2_rn(oacc[nt][0] * inv_lo, oacc[nt][1] * inv_lo);
        *(__half2*)(po_hi + col) = __floats2half2_rn(oacc[nt][2] * inv_hi, oacc[nt][3] * inv_hi);
    }
}

// ---------------- host launcher ----------------
extern "C" void kernel_launch(void* const* d_in, const int* in_sizes, int n_in,
                              void* d_out, int out_size)
{
    const float* x      = (const float*)d_in[0];
    const float* w_qkv  = (const float*)d_in[1];
    const float* b_qkv  = (const float*)d_in[2];
    const float* q_g    = (const float*)d_in[3];
    const float* q_b    = (const float*)d_in[4];
    const float* k_g    = (const float*)d_in[5];
    const float* k_b    = (const float*)d_in[6];
    const float* w_proj = (const float*)d_in[7];
    const float* b_proj = (const float*)d_in[8];
    float* out = (float*)d_out;

    void *p_qkv, *p_x16, *p_wqkv16, *p_wproj16, *p_qt, *p_kt, *p_vt, *p_ao;
    cudaGetSymbolAddress(&p_qkv,     g_qkv);
    cudaGetSymbolAddress(&p_x16,     g_x16);
    cudaGetSymbolAddress(&p_wqkv16,  g_wqkv16);
    cudaGetSymbolAddress(&p_wproj16, g_wproj16);
    cudaGetSymbolAddress(&p_qt,      g_qt);
    cudaGetSymbolAddress(&p_kt,      g_kt);
    cudaGetSymbolAddress(&p_vt,      g_vt);
    cudaGetSymbolAddress(&p_ao,      g_ao);

    const int smemG = 4 * 256 * 40 * 2;   // 81920 B per CTA
    cudaFuncSetAttribute(hgemm, cudaFuncAttributeMaxDynamicSharedMemorySize, smemG);
    cudaFuncSetAttribute(flash_attn, cudaFuncAttributeMaxDynamicSharedMemorySize, SM_FLASH);

    // 0) fp32 -> fp16 conversion
    const int n0 = MROWS * DIM / 4, n1 = O3 * DIM / 4, n2 = DIM * DIM / 4;
    f2h3<<<(n0 + n1 + n2 + 255) / 256, 256>>>(
        x, (__half*)p_x16, n0,
        w_qkv, (__half*)p_wqkv16, n1,
        w_proj, (__half*)p_wproj16, n2);

    // 1) QKV GEMM
    hgemm<<<dim3(O3 / 128, MROWS / 128), 128, smemG>>>(
        (const __half*)p_x16, (const __half*)p_wqkv16, b_qkv, (float*)p_qkv,
        DIM, DIM, DIM, O3);

    // 2) LayerNorm + transpose -> fp16
    ln_split<<<(BATCH * SEQ * NHEAD) / 8, 256>>>(
        (const float*)p_qkv, q_g, q_b, k_g, k_b,
        (__half*)p_qt, (__half*)p_kt, (__half*)p_vt);

    // 3) fused attention
    flash_attn<<<dim3(SEQ / 128, BH), 256, SM_FLASH>>>(
        (const __half*)p_qt, (const __half*)p_kt, (const __half*)p_vt, (__half*)p_ao);

    // 4) projection
    hgemm<<<dim3(DIM / 128, MROWS / 128), 128, smemG>>>(
        (const __half*)p_ao, (const __half*)p_wproj16, b_proj, out,
        DIM, DIM, DIM, DIM);
}

// round 9
// speedup vs baseline: 9.9670x; 1.0327x over previous
#include <cuda_runtime.h>
#include <cuda_fp16.h>
#include <cstdint>
#include <math.h>
#include <float.h>

#define BATCH 2
#define SEQ   2048
#define DIM   1152
#define NHEAD 16
#define HDIM  72
#define QKPAD 80
#define O3    (3 * DIM)
#define MROWS (BATCH * SEQ)    // 4096
#define BH    (BATCH * NHEAD)  // 32
#define SCALE 0.1178511301977579f
#define QSC   (0.1178511301977579f * 1.4426950408889634f)   // SCALE * log2(e)
#define LN_EPS 1e-5f

// ---------------- scratch ----------------
__device__ float  g_qkv[(size_t)MROWS * O3];
__device__ __half g_x16[(size_t)MROWS * DIM];
__device__ __half g_wqkv16[(size_t)O3 * DIM];
__device__ __half g_wproj16[(size_t)DIM * DIM];
__device__ __half g_qt[(size_t)BH * SEQ * QKPAD];     // QSC folded
__device__ __half g_kt[(size_t)BH * SEQ * QKPAD];
__device__ __half g_vt[(size_t)BH * SEQ * HDIM];      // natural [bh][n][72]
__device__ __half g_ao[(size_t)MROWS * DIM];

__device__ __forceinline__ uint32_t packh2(float x, float y) {
    __half2 h = __floats2half2_rn(x, y);
    return *(uint32_t*)&h;
}
__device__ __forceinline__ uint32_t s2u(const void* p) {
    return (uint32_t)__cvta_generic_to_shared(p);
}
__device__ __forceinline__ float ex2f(float x) {
    float r; asm("ex2.approx.f32 %0, %1;" : "=f"(r) : "f"(x)); return r;
}
// pack two fp32 deltas to half2, then packed ex2 -> ready-to-use mma fragment
__device__ __forceinline__ uint32_t ex2h2(float x, float y) {
    uint32_t p = packh2(x, y);
    uint32_t r;
    asm("ex2.approx.f16x2 %0, %1;" : "=r"(r) : "r"(p));
    return r;
}
__device__ __forceinline__ void mma16(float c[4], const uint32_t a[4], const uint32_t b[2]) {
    asm volatile(
        "mma.sync.aligned.m16n8k16.row.col.f32.f16.f16.f32 "
        "{%0,%1,%2,%3}, {%4,%5,%6,%7}, {%8,%9}, {%0,%1,%2,%3};"
        : "+f"(c[0]), "+f"(c[1]), "+f"(c[2]), "+f"(c[3])
        : "r"(a[0]), "r"(a[1]), "r"(a[2]), "r"(a[3]), "r"(b[0]), "r"(b[1]));
}
__device__ __forceinline__ void ldm4(uint32_t r[4], uint32_t a) {
    asm volatile("ldmatrix.sync.aligned.m8n8.x4.shared.b16 {%0,%1,%2,%3}, [%4];"
        : "=r"(r[0]), "=r"(r[1]), "=r"(r[2]), "=r"(r[3]) : "r"(a));
}
__device__ __forceinline__ void ldm4t(uint32_t r[4], uint32_t a) {
    asm volatile("ldmatrix.sync.aligned.m8n8.x4.trans.shared.b16 {%0,%1,%2,%3}, [%4];"
        : "=r"(r[0]), "=r"(r[1]), "=r"(r[2]), "=r"(r[3]) : "r"(a));
}
__device__ __forceinline__ void ldm2t(uint32_t r[2], uint32_t a) {
    asm volatile("ldmatrix.sync.aligned.m8n8.x2.trans.shared.b16 {%0,%1}, [%2];"
        : "=r"(r[0]), "=r"(r[1]) : "r"(a));
}
__device__ __forceinline__ void cp16(uint32_t dst, const void* src) {
    asm volatile("cp.async.ca.shared.global [%0], [%1], 16;" :: "r"(dst), "l"(src));
}
#define CP_COMMIT() asm volatile("cp.async.commit_group;" ::: "memory")
#define CP_WAIT1()  asm volatile("cp.async.wait_group 1;" ::: "memory")
#define CP_WAIT2()  asm volatile("cp.async.wait_group 2;" ::: "memory")

// ---------------- fused fp32 -> fp16 convert ----------------
__global__ void f2h3(const float* __restrict__ s0, __half* __restrict__ d0, int n0,
                     const float* __restrict__ s1, __half* __restrict__ d1, int n1,
                     const float* __restrict__ s2, __half* __restrict__ d2, int n2)
{
    int i = blockIdx.x * blockDim.x + threadIdx.x;
    const float* s; __half* d; int j;
    if (i < n0)                { s = s0; d = d0; j = i; }
    else if (i < n0 + n1)      { s = s1; d = d1; j = i - n0; }
    else if (i < n0 + n1 + n2) { s = s2; d = d2; j = i - n0 - n1; }
    else return;
    float4 v = ((const float4*)s)[j];
    ((uint2*)d)[j] = make_uint2(packh2(v.x, v.y), packh2(v.z, v.w));
}

// ================= fp16 GEMM: 128x128 block, 128 thr, 4-stage, 2 CTA/SM ======
__global__ __launch_bounds__(128)
void hgemm(const __half* __restrict__ A, const __half* __restrict__ B,
           const float* __restrict__ bias, float* __restrict__ C,
           int K, int lda, int ldb, int ldc)
{
    extern __shared__ __half smh[];
    constexpr int PAD = 40;              // 80 B pitch
    constexpr int STG = 256 * PAD;
    constexpr int BOF = 128 * PAD;

    const int tid = threadIdx.x, wid = tid >> 5, lane = tid & 31;
    const int g = lane >> 2, t = lane & 3;
    const int l8 = lane & 7, mi = lane >> 3;
    const int mrow = (mi & 1) * 8 + l8;
    const int mkof = (mi >> 1) * 8;
    const int wm = wid >> 1, wn = wid & 1;
    const int m0 = blockIdx.y * 128, n0 = blockIdx.x * 128;
    const int ar = tid >> 2, ac = (tid & 3) * 8;

    const uint32_t sb = s2u(smh);

    float acc[4][8][4];
#pragma unroll
    for (int mt = 0; mt < 4; mt++)
#pragma unroll
        for (int nt = 0; nt < 8; nt++)
#pragma unroll
            for (int j = 0; j < 4; j++) acc[mt][nt][j] = 0.f;

    auto load_chunk = [&](int c) {
        const int k0 = c * 32;
        const uint32_t da = sb + ((c & 3) * STG) * 2;
        const uint32_t db = da + BOF * 2;
#pragma unroll
        for (int i = 0; i < 4; i++) {
            cp16(da + ((ar + i * 32) * PAD + ac) * 2,
                 A + (size_t)(m0 + ar + i * 32) * lda + k0 + ac);
            cp16(db + ((ar + i * 32) * PAD + ac) * 2,
                 B + (size_t)(n0 + ar + i * 32) * ldb + k0 + ac);
        }
    };

    const int nch = K / 32;
    load_chunk(0); CP_COMMIT();
    load_chunk(1); CP_COMMIT();
    load_chunk(2); CP_COMMIT();

    for (int c = 0; c < nch; c++) {
        CP_WAIT2();
        __syncthreads();
        if (c + 3 < nch) load_chunk(c + 3);
        CP_COMMIT();

        const uint32_t ab = sb + ((c & 3) * STG) * 2;
        const uint32_t bb = ab + BOF * 2;
#pragma unroll
        for (int ks = 0; ks < 2; ks++) {
            const int kk = ks * 16;
            uint32_t af[4][4], bf[4][4];
#pragma unroll
            for (int mt = 0; mt < 4; mt++)
                ldm4(af[mt], ab + ((wm * 64 + mt * 16 + mrow) * PAD + kk + mkof) * 2);
#pragma unroll
            for (int np = 0; np < 4; np++)
                ldm4(bf[np], bb + ((wn * 64 + np * 16 + mrow) * PAD + kk + mkof) * 2);
#pragma unroll
            for (int mt = 0; mt < 4; mt++)
#pragma unroll
                for (int np = 0; np < 4; np++) {
                    uint32_t b0[2] = { bf[np][0], bf[np][2] };
                    uint32_t b1[2] = { bf[np][1], bf[np][3] };
                    mma16(acc[mt][2 * np],     af[mt], b0);
                    mma16(acc[mt][2 * np + 1], af[mt], b1);
                }
        }
    }

#pragma unroll
    for (int mt = 0; mt < 4; mt++) {
        const int r0 = m0 + wm * 64 + mt * 16 + g;
#pragma unroll
        for (int nt = 0; nt < 8; nt++) {
            const int col = n0 + wn * 64 + nt * 8 + 2 * t;
            const float bx = bias[col], by = bias[col + 1];
            *(float2*)(C + (size_t)r0 * ldc + col) =
                make_float2(acc[mt][nt][0] + bx, acc[mt][nt][1] + by);
            *(float2*)(C + (size_t)(r0 + 8) * ldc + col) =
                make_float2(acc[mt][nt][2] + bx, acc[mt][nt][3] + by);
        }
    }
}

// ------------- LayerNorm(q,k) + QSC + transpose -> fp16; V natural layout ----
__global__ __launch_bounds__(256)
void ln_split(const float* __restrict__ qkv,
              const float* __restrict__ qg, const float* __restrict__ qb,
              const float* __restrict__ kg, const float* __restrict__ kb,
              __half* __restrict__ qt, __half* __restrict__ kt, __half* __restrict__ vt)
{
    int task = blockIdx.x * 8 + (threadIdx.x >> 5);
    if (task >= BATCH * SEQ * NHEAD) return;
    const int lane = threadIdx.x & 31;
    const int h = task % NHEAD;
    const int n = (task / NHEAD) % SEQ;
    const int b = task / (NHEAD * SEQ);
    const int bh = b * NHEAD + h;

    const size_t ibase = ((size_t)(b * SEQ + n) * 3) * DIM + h * HDIM;
    const size_t oqk = ((size_t)bh * SEQ + n) * QKPAD;

    const float* q = qkv + ibase;
    const float* k = qkv + ibase + DIM;
    const float* v = qkv + ibase + 2 * DIM;

    {
        float x0 = q[lane], x1 = q[lane + 32];
        float x2 = (lane < 8) ? q[lane + 64] : 0.f;
        float s = x0 + x1 + x2;
#pragma unroll
        for (int o = 16; o; o >>= 1) s += __shfl_xor_sync(0xffffffffu, s, o);
        const float mu = s * (1.0f / HDIM);
        float d0 = x0 - mu, d1 = x1 - mu, d2 = (lane < 8) ? (x2 - mu) : 0.f;
        float vs = d0 * d0 + d1 * d1 + d2 * d2;
#pragma unroll
        for (int o = 16; o; o >>= 1) vs += __shfl_xor_sync(0xffffffffu, vs, o);
        const float inv = rsqrtf(vs * (1.0f / HDIM) + LN_EPS);
        qt[oqk + lane]      = __float2half_rn((d0 * inv * qg[lane]      + qb[lane])      * QSC);
        qt[oqk + lane + 32] = __float2half_rn((d1 * inv * qg[lane + 32] + qb[lane + 32]) * QSC);
        if (lane < 16)
            qt[oqk + lane + 64] = __float2half_rn((lane < 8) ?
                (d2 * inv * qg[lane + 64] + qb[lane + 64]) * QSC : 0.f);
    }
    {
        float x0 = k[lane], x1 = k[lane + 32];
        float x2 = (lane < 8) ? k[lane + 64] : 0.f;
        float s = x0 + x1 + x2;
#pragma unroll
        for (int o = 16; o; o >>= 1) s += __shfl_xor_sync(0xffffffffu, s, o);
        const float mu = s * (1.0f / HDIM);
        float d0 = x0 - mu, d1 = x1 - mu, d2 = (lane < 8) ? (x2 - mu) : 0.f;
        float vs = d0 * d0 + d1 * d1 + d2 * d2;
#pragma unroll
        for (int o = 16; o; o >>= 1) vs += __shfl_xor_sync(0xffffffffu, vs, o);
        const float inv = rsqrtf(vs * (1.0f / HDIM) + LN_EPS);
        kt[oqk + lane]      = __float2half_rn(d0 * inv * kg[lane]      + kb[lane]);
        kt[oqk + lane + 32] = __float2half_rn(d1 * inv * kg[lane + 32] + kb[lane + 32]);
        if (lane < 16)
            kt[oqk + lane + 64] = __float2half_rn((lane < 8) ?
                (d2 * inv * kg[lane + 64] + kb[lane + 64]) : 0.f);
    }
    {
        __half* vb = vt + ((size_t)bh * SEQ + n) * HDIM;
        vb[lane]      = __float2half_rn(v[lane]);
        vb[lane + 32] = __float2half_rn(v[lane + 32]);
        if (lane < 8) vb[lane + 64] = __float2half_rn(v[lane + 64]);
    }
}

// ================= fused flash attention v5 =================
// ones-column row-sum, log2-domain softmax with ex2.f16x2 fused pack,
// softmax interleaved into PV j-loop, ballot-skip rescale, 2 CTA/SM.
#define TK 64
#define NTI (SEQ / TK)          // 32
#define QSTR 88                 // 176 B pitch
#define VSTR 88                 // col 72 = 1.0, 73..79 = 0
#define SMH_Q 0
#define SMH_K (128 * QSTR)
#define SMH_V (SMH_K + 3 * TK * QSTR)
#define SM_FLASH ((SMH_V + 3 * TK * VSTR) * 2)    // 90112 B

__global__ __launch_bounds__(256, 2)
void flash_attn(const __half* __restrict__ qt, const __half* __restrict__ kt,
                const __half* __restrict__ vt, __half* __restrict__ ao)
{
    extern __shared__ __half smh[];
    const int tid = threadIdx.x, wid = tid >> 5, lane = tid & 31;
    const int g = lane >> 2, t = lane & 3;
    const int l8 = lane & 7, mi = lane >> 3;
    const int mrow = (mi & 1) * 8 + l8;
    const int mkof = (mi >> 1) * 8;
    const int m0 = blockIdx.x * 128;
    const int bh = blockIdx.y;

    const __half* Qg = qt + ((size_t)bh * SEQ + m0) * QKPAD;
    const __half* Kg = kt + (size_t)bh * SEQ * QKPAD;
    const __half* Vg = vt + (size_t)bh * SEQ * HDIM;

    const uint32_t sb = s2u(smh);

    for (int idx = tid; idx < 1280; idx += 256) {
        int r = idx / 10, c8 = (idx % 10) * 8;
        *(uint4*)(smh + SMH_Q + r * QSTR + c8) = *(const uint4*)(Qg + (size_t)r * QKPAD + c8);
    }
    if (tid < 3 * TK) {   // V cols 72..79: {1,0,0,0,0,0,0,0}
        uint4 ones = make_uint4(0x00003C00u, 0u, 0u, 0u);
        *(uint4*)(smh + SMH_V + tid * VSTR + 72) = ones;
    }

    auto load_kv = [&](int ti, int buf) {
        const int n0 = ti * TK;
        const uint32_t kd = sb + (SMH_K + buf * TK * QSTR) * 2;
#pragma unroll
        for (int i = 0; i < 3; i++) {
            int idx = tid + i * 256;
            if (idx < 640) {
                int r = idx / 10, c8 = (idx % 10) * 8;
                cp16(kd + (r * QSTR + c8) * 2, Kg + (size_t)(n0 + r) * QKPAD + c8);
            }
        }
        const uint32_t vd = sb + (SMH_V + buf * TK * VSTR) * 2;
#pragma unroll
        for (int i = 0; i < 3; i++) {
            int idx = tid + i * 256;
            if (idx < 576) {
                int r = idx / 9, c8 = (idx % 9) * 8;
                cp16(vd + (r * VSTR + c8) * 2, Vg + (size_t)(n0 + r) * HDIM + c8);
            }
        }
    };

    load_kv(0, 0); CP_COMMIT();
    load_kv(1, 1); CP_COMMIT();

    float m_lo = -1e30f, m_hi = -1e30f;
    float oacc[10][4];
#pragma unroll
    for (int nt = 0; nt < 10; nt++)
#pragma unroll
        for (int j = 0; j < 4; j++) oacc[nt][j] = 0.f;

    uint32_t qf[5][4];
    bool qloaded = false;
    int bufL = 2, bufC = 0;

    for (int ti = 0; ti < NTI; ti++) {
        CP_WAIT1();
        __syncthreads();
        if (ti + 2 < NTI) load_kv(ti + 2, bufL);
        CP_COMMIT();
        bufL = (bufL == 2) ? 0 : bufL + 1;

        if (!qloaded) {
            qloaded = true;
#pragma unroll
            for (int s = 0; s < 5; s++)
                ldm4(qf[s], sb + (SMH_Q + (wid * 16 + mrow) * QSTR + s * 16 + mkof) * 2);
        }
        const uint32_t kbase = sb + (SMH_K + bufC * TK * QSTR) * 2;
        const uint32_t vbase = sb + (SMH_V + bufC * TK * VSTR) * 2;
        bufC = (bufC == 2) ? 0 : bufC + 1;

        // ---- S = Q @ K^T (log2 domain) ----
        float sacc[8][4];
#pragma unroll
        for (int nt = 0; nt < 8; nt++)
#pragma unroll
            for (int j = 0; j < 4; j++) sacc[nt][j] = 0.f;
#pragma unroll
        for (int s = 0; s < 5; s++) {
#pragma unroll
            for (int np = 0; np < 4; np++) {
                uint32_t kf[4];
                ldm4(kf, kbase + ((np * 16 + mrow) * QSTR + s * 16 + mkof) * 2);
                uint32_t b0[2] = { kf[0], kf[2] }, b1[2] = { kf[1], kf[3] };
                mma16(sacc[2 * np],     qf[s], b0);
                mma16(sacc[2 * np + 1], qf[s], b1);
            }
        }

        // ---- running max + rescale ----
        float mx_lo = -1e30f, mx_hi = -1e30f;
#pragma unroll
        for (int nt = 0; nt < 8; nt++) {
            mx_lo = fmaxf(mx_lo, fmaxf(sacc[nt][0], sacc[nt][1]));
            mx_hi = fmaxf(mx_hi, fmaxf(sacc[nt][2], sacc[nt][3]));
        }
        mx_lo = fmaxf(mx_lo, __shfl_xor_sync(0xffffffffu, mx_lo, 1));
        mx_lo = fmaxf(mx_lo, __shfl_xor_sync(0xffffffffu, mx_lo, 2));
        mx_hi = fmaxf(mx_hi, __shfl_xor_sync(0xffffffffu, mx_hi, 1));
        mx_hi = fmaxf(mx_hi, __shfl_xor_sync(0xffffffffu, mx_hi, 2));

        const float mn_lo = fmaxf(m_lo, mx_lo), mn_hi = fmaxf(m_hi, mx_hi);
        const float al_lo = ex2f(m_lo - mn_lo), al_hi = ex2f(m_hi - mn_hi);
        m_lo = mn_lo; m_hi = mn_hi;

        if (__ballot_sync(0xffffffffu, (al_lo != 1.f) || (al_hi != 1.f))) {
#pragma unroll
            for (int nt = 0; nt < 10; nt++) {
                oacc[nt][0] *= al_lo; oacc[nt][1] *= al_lo;
                oacc[nt][2] *= al_hi; oacc[nt][3] *= al_hi;
            }
        }

        // ---- P = 2^(S - mn) packed fp16x2, interleaved with O += P @ V ----
#pragma unroll
        for (int j = 0; j < 4; j++) {
            uint32_t a[4] = {
                ex2h2(sacc[2 * j][0]     - mn_lo, sacc[2 * j][1]     - mn_lo),
                ex2h2(sacc[2 * j][2]     - mn_hi, sacc[2 * j][3]     - mn_hi),
                ex2h2(sacc[2 * j + 1][0] - mn_lo, sacc[2 * j + 1][1] - mn_lo),
                ex2h2(sacc[2 * j + 1][2] - mn_hi, sacc[2 * j + 1][3] - mn_hi) };
            const uint32_t vrow = vbase + ((j * 16 + mrow) * VSTR) * 2;
#pragma unroll
            for (int np = 0; np < 4; np++) {
                uint32_t vf[4];
                ldm4t(vf, vrow + np * 32 + (mi >> 1) * 16);
                uint32_t b0[2] = { vf[0], vf[1] }, b1[2] = { vf[2], vf[3] };
                mma16(oacc[2 * np],     a, b0);
                mma16(oacc[2 * np + 1], a, b1);
            }
            {
                uint32_t v2[2];
                ldm2t(v2, vrow + 128);       // cols 64..71
                mma16(oacc[8], a, v2);
            }
            {
                uint32_t v2[2];
                ldm2t(v2, vrow + 144);       // cols 72..79 (ones column)
                mma16(oacc[9], a, v2);
            }
        }
    }

    // ---- epilogue: l from ones column ----
    const float l_lo = __shfl_sync(0xffffffffu, oacc[9][0], lane & 28);
    const float l_hi = __shfl_sync(0xffffffffu, oacc[9][2], lane & 28);
    const float inv_lo = 1.f / l_lo, inv_hi = 1.f / l_hi;
    const int b = bh >> 4, h = bh & 15;
    const int n_lo = m0 + wid * 16 + g;
    __half* po_lo = ao + ((size_t)(b * SEQ) + n_lo) * DIM + h * HDIM;
    __half* po_hi = po_lo + (size_t)8 * DIM;
#pragma unroll
    for (int nt = 0; nt < 9; nt++) {
        const int col = nt * 8 + 2 * t;
        *(__half2*)(po_lo + col) = __floats2half2_rn(oacc[nt][0] * inv_lo, oacc[nt][1] * inv_lo);
        *(__half2*)(po_hi + col) = __floats2half2_rn(oacc[nt][2] * inv_hi, oacc[nt][3] * inv_hi);
    }
}

// ---------------- host launcher ----------------
extern "C" void kernel_launch(void* const* d_in, const int* in_sizes, int n_in,
                              void* d_out, int out_size)
{
    const float* x      = (const float*)d_in[0];
    const float* w_qkv  = (const float*)d_in[1];
    const float* b_qkv  = (const float*)d_in[2];
    const float* q_g    = (const float*)d_in[3];
    const float* q_b    = (const float*)d_in[4];
    const float* k_g    = (const float*)d_in[5];
    const float* k_b    = (const float*)d_in[6];
    const float* w_proj = (const float*)d_in[7];
    const float* b_proj = (const float*)d_in[8];
    float* out = (float*)d_out;

    void *p_qkv, *p_x16, *p_wqkv16, *p_wproj16, *p_qt, *p_kt, *p_vt, *p_ao;
    cudaGetSymbolAddress(&p_qkv,     g_qkv);
    cudaGetSymbolAddress(&p_x16,     g_x16);
    cudaGetSymbolAddress(&p_wqkv16,  g_wqkv16);
    cudaGetSymbolAddress(&p_wproj16, g_wproj16);
    cudaGetSymbolAddress(&p_qt,      g_qt);
    cudaGetSymbolAddress(&p_kt,      g_kt);
    cudaGetSymbolAddress(&p_vt,      g_vt);
    cudaGetSymbolAddress(&p_ao,      g_ao);

    const int smemG = 4 * 256 * 40 * 2;   // 81920 B per CTA
    cudaFuncSetAttribute(hgemm, cudaFuncAttributeMaxDynamicSharedMemorySize, smemG);
    cudaFuncSetAttribute(flash_attn, cudaFuncAttributeMaxDynamicSharedMemorySize, SM_FLASH);

    // 0) fp32 -> fp16 conversion
    const int n0 = MROWS * DIM / 4, n1 = O3 * DIM / 4, n2 = DIM * DIM / 4;
    f2h3<<<(n0 + n1 + n2 + 255) / 256, 256>>>(
        x, (__half*)p_x16, n0,
        w_qkv, (__half*)p_wqkv16, n1,
        w_proj, (__half*)p_wproj16, n2);

    // 1) QKV GEMM
    hgemm<<<dim3(O3 / 128, MROWS / 128), 128, smemG>>>(
        (const __half*)p_x16, (const __half*)p_wqkv16, b_qkv, (float*)p_qkv,
        DIM, DIM, DIM, O3);

    // 2) LayerNorm + transpose -> fp16
    ln_split<<<(BATCH * SEQ * NHEAD) / 8, 256>>>(
        (const float*)p_qkv, q_g, q_b, k_g, k_b,
        (__half*)p_qt, (__half*)p_kt, (__half*)p_vt);

    // 3) fused attention
    flash_attn<<<dim3(SEQ / 128, BH), 256, SM_FLASH>>>(
        (const __half*)p_qt, (const __half*)p_kt, (const __half*)p_vt, (__half*)p_ao);

    // 4) projection
    hgemm<<<dim3(DIM / 128, MROWS / 128), 128, smemG>>>(
        (const __half*)p_ao, (const __half*)p_wproj16, b_proj, out,
        DIM, DIM, DIM, DIM);
}